// round 5
// baseline (speedup 1.0000x reference)
#include <cuda_runtime.h>
#include <cuda_bf16.h>
#include <math.h>
#include <stdint.h>

#define B_   2
#define S_   2048
#define D_   1024
#define H_   16
#define HD_  64
#define GLB  16
#define HALFW 32

#define MTOT (B_*S_)   // 4096

// ---------------- scratch ------------------------------------------------------
__device__ __align__(16) float g_Q[MTOT * D_];
__device__ __align__(16) float g_K[MTOT * D_];
__device__ __align__(16) float g_V[MTOT * D_];

__device__ __align__(16) __nv_bfloat16 g_qh[MTOT * D_], g_ql[MTOT * D_];
__device__ __align__(16) __nv_bfloat16 g_kh[MTOT * D_], g_kl[MTOT * D_];
__device__ __align__(16) __nv_bfloat16 g_vh[MTOT * D_], g_vl[MTOT * D_];
__device__ __align__(16) __nv_bfloat16 g_ch[MTOT * D_], g_cl[MTOT * D_];
__device__ __align__(16) __nv_bfloat16 g_wqh[D_ * D_], g_wql[D_ * D_];
__device__ __align__(16) __nv_bfloat16 g_wkh[D_ * D_], g_wkl[D_ * D_];
__device__ __align__(16) __nv_bfloat16 g_wvh[D_ * D_], g_wvl[D_ * D_];
__device__ __align__(16) __nv_bfloat16 g_woh[D_ * D_], g_wol[D_ * D_];

__device__ __forceinline__ uint32_t smem_u32(const void* p) {
    uint32_t a;
    asm("{ .reg .u64 t; cvta.to.shared.u64 t, %1; cvt.u32.u64 %0, t; }"
        : "=r"(a) : "l"(p));
    return a;
}
#define CPA16(daddr, gptr) \
    asm volatile("cp.async.ca.shared.global [%0], [%1], 16;" :: "r"(daddr), "l"(gptr))
#define CP_COMMIT() asm volatile("cp.async.commit_group;")
#define CP_WAIT1()  asm volatile("cp.async.wait_group 1;")

__device__ __forceinline__ void f2bf_hilo(float x, __nv_bfloat16& h, __nv_bfloat16& l) {
    h = __float2bfloat16_rn(x);
    l = __float2bfloat16_rn(x - __bfloat162float(h));
}

// ---------------- fp32 -> bf16 hi/lo pre-convert --------------------------------
struct CvtArgs { const float* in; __nv_bfloat16* h; __nv_bfloat16* l; };

__global__ __launch_bounds__(256) void cvt_hilo(
    CvtArgs c0, CvtArgs c1, CvtArgs c2, CvtArgs c3, int n)
{
    CvtArgs c = (blockIdx.z == 0) ? c0 : (blockIdx.z == 1) ? c1 :
                (blockIdx.z == 2) ? c2 : c3;
    const int stride = gridDim.x * blockDim.x * 4;
    for (int i = (blockIdx.x * blockDim.x + threadIdx.x) * 4; i < n; i += stride) {
        float4 v = *(const float4*)(c.in + i);
        __nv_bfloat16 h0, h1, h2, h3, l0, l1, l2, l3;
        f2bf_hilo(v.x, h0, l0); f2bf_hilo(v.y, h1, l1);
        f2bf_hilo(v.z, h2, l2); f2bf_hilo(v.w, h3, l3);
        uint2 hp, lp;
        hp.x = (uint32_t)__bfloat16_as_ushort(h0) | ((uint32_t)__bfloat16_as_ushort(h1) << 16);
        hp.y = (uint32_t)__bfloat16_as_ushort(h2) | ((uint32_t)__bfloat16_as_ushort(h3) << 16);
        lp.x = (uint32_t)__bfloat16_as_ushort(l0) | ((uint32_t)__bfloat16_as_ushort(l1) << 16);
        lp.y = (uint32_t)__bfloat16_as_ushort(l2) | ((uint32_t)__bfloat16_as_ushort(l3) << 16);
        *(uint2*)(c.h + i) = hp;
        *(uint2*)(c.l + i) = lp;
    }
}

// ---------------- HMMA GEMM (bf16x3, cp.async double-buffered) ------------------
struct GemmB {
    const __nv_bfloat16 *Ah, *Al, *Wh, *Wl;
    const float* bias;
    float* C;
};

#define SROW 40                         // padded row: 80 bytes (16B multiple)
#define TILE_BYTES (128 * SROW * 2)     // 10240
#define GEMM_SMEM  (2 * 4 * TILE_BYTES) // 81920

__device__ __forceinline__ uint32_t lds32(const char* base, int row, int k) {
    return *(const uint32_t*)(base + row * (SROW * 2) + k * 2);
}

__device__ __forceinline__ void mma16816(
    float& d0, float& d1, float& d2, float& d3,
    uint32_t a0, uint32_t a1, uint32_t a2, uint32_t a3,
    uint32_t b0, uint32_t b1)
{
    asm volatile(
        "mma.sync.aligned.m16n8k16.row.col.f32.bf16.bf16.f32 "
        "{%0,%1,%2,%3}, {%4,%5,%6,%7}, {%8,%9}, {%0,%1,%2,%3};"
        : "+f"(d0), "+f"(d1), "+f"(d2), "+f"(d3)
        : "r"(a0), "r"(a1), "r"(a2), "r"(a3), "r"(b0), "r"(b1));
}

__global__ __launch_bounds__(256) void gemm_mma(GemmB g0, GemmB g1, GemmB g2)
{
    GemmB g = (blockIdx.z == 0) ? g0 : ((blockIdx.z == 1) ? g1 : g2);

    extern __shared__ __align__(16) char dsm[];
    const uint32_t sb = smem_u32(dsm);

    const int tid  = threadIdx.x;
    const int wid  = tid >> 5;
    const int lane = tid & 31;
    const int bm = blockIdx.y * 128;
    const int bn = blockIdx.x * 128;
    const int warp_m = (wid & 1) * 64;
    const int warp_n = (wid >> 1) * 32;

    const int grow = tid >> 1;
    const int gk   = (tid & 1) << 4;
    const __nv_bfloat16* pAh = g.Ah + (size_t)(bm + grow) * D_ + gk;
    const __nv_bfloat16* pAl = g.Al + (size_t)(bm + grow) * D_ + gk;
    const __nv_bfloat16* pBh = g.Wh + (size_t)(bn + grow) * D_ + gk;
    const __nv_bfloat16* pBl = g.Wl + (size_t)(bn + grow) * D_ + gk;
    const uint32_t soff = (uint32_t)(grow * (SROW * 2) + gk * 2);

    float acc[4][4][4];
#pragma unroll
    for (int mt = 0; mt < 4; mt++)
#pragma unroll
        for (int nt = 0; nt < 4; nt++)
#pragma unroll
            for (int q = 0; q < 4; q++) acc[mt][nt][q] = 0.f;

    const int fr = lane >> 2;
    const int fk = (lane & 3) << 1;

#define ISSUE(chunk, stage) do {                                            \
        const int _off = (chunk) * 32;                                      \
        const uint32_t _s = sb + (stage) * 4 * TILE_BYTES + soff;           \
        CPA16(_s + 0 * TILE_BYTES,      pAh + _off);                        \
        CPA16(_s + 0 * TILE_BYTES + 16, pAh + _off + 8);                    \
        CPA16(_s + 1 * TILE_BYTES,      pAl + _off);                        \
        CPA16(_s + 1 * TILE_BYTES + 16, pAl + _off + 8);                    \
        CPA16(_s + 2 * TILE_BYTES,      pBh + _off);                        \
        CPA16(_s + 2 * TILE_BYTES + 16, pBh + _off + 8);                    \
        CPA16(_s + 3 * TILE_BYTES,      pBl + _off);                        \
        CPA16(_s + 3 * TILE_BYTES + 16, pBl + _off + 8);                    \
    } while (0)

    ISSUE(0, 0); CP_COMMIT();
    ISSUE(1, 1); CP_COMMIT();

    for (int c = 0; c < 32; ++c) {
        CP_WAIT1();
        __syncthreads();
        const char* base = dsm + (c & 1) * 4 * TILE_BYTES;
        const char* sAh = base;
        const char* sAl = base + TILE_BYTES;
        const char* sBh = base + 2 * TILE_BYTES;
        const char* sBl = base + 3 * TILE_BYTES;

#pragma unroll
        for (int ks = 0; ks < 2; ++ks) {
            const int kk = ks * 16 + fk;
            uint32_t ah[4][4];
#pragma unroll
            for (int mt = 0; mt < 4; mt++) {
                const int r = warp_m + mt * 16 + fr;
                ah[mt][0] = lds32(sAh, r,     kk);
                ah[mt][1] = lds32(sAh, r + 8, kk);
                ah[mt][2] = lds32(sAh, r,     kk + 8);
                ah[mt][3] = lds32(sAh, r + 8, kk + 8);
            }
            uint32_t bh[4][2];
#pragma unroll
            for (int nt = 0; nt < 4; nt++) {
                const int n = warp_n + nt * 8 + fr;
                bh[nt][0] = lds32(sBh, n, kk);
                bh[nt][1] = lds32(sBh, n, kk + 8);
            }
#pragma unroll
            for (int mt = 0; mt < 4; mt++)
#pragma unroll
                for (int nt = 0; nt < 4; nt++)
                    mma16816(acc[mt][nt][0], acc[mt][nt][1], acc[mt][nt][2], acc[mt][nt][3],
                             ah[mt][0], ah[mt][1], ah[mt][2], ah[mt][3],
                             bh[nt][0], bh[nt][1]);
#pragma unroll
            for (int mt = 0; mt < 4; mt++) {
                const int r = warp_m + mt * 16 + fr;
                uint32_t al0 = lds32(sAl, r,     kk);
                uint32_t al1 = lds32(sAl, r + 8, kk);
                uint32_t al2 = lds32(sAl, r,     kk + 8);
                uint32_t al3 = lds32(sAl, r + 8, kk + 8);
#pragma unroll
                for (int nt = 0; nt < 4; nt++)
                    mma16816(acc[mt][nt][0], acc[mt][nt][1], acc[mt][nt][2], acc[mt][nt][3],
                             al0, al1, al2, al3, bh[nt][0], bh[nt][1]);
            }
#pragma unroll
            for (int nt = 0; nt < 4; nt++) {
                const int n = warp_n + nt * 8 + fr;
                uint32_t bl0 = lds32(sBl, n, kk);
                uint32_t bl1 = lds32(sBl, n, kk + 8);
#pragma unroll
                for (int mt = 0; mt < 4; mt++)
                    mma16816(acc[mt][nt][0], acc[mt][nt][1], acc[mt][nt][2], acc[mt][nt][3],
                             ah[mt][0], ah[mt][1], ah[mt][2], ah[mt][3],
                             bl0, bl1);
            }
        }
        __syncthreads();
        if (c + 2 < 32) ISSUE(c + 2, c & 1);
        CP_COMMIT();
    }
#undef ISSUE

#pragma unroll
    for (int mt = 0; mt < 4; mt++) {
        const int r0 = bm + warp_m + mt * 16 + fr;
#pragma unroll
        for (int nt = 0; nt < 4; nt++) {
            const int col = bn + warp_n + nt * 8 + fk;
            const float b0 = g.bias[col], b1 = g.bias[col + 1];
            float2 v0 = make_float2(acc[mt][nt][0] + b0, acc[mt][nt][1] + b1);
            float2 v1 = make_float2(acc[mt][nt][2] + b0, acc[mt][nt][3] + b1);
            *(float2*)(g.C + (size_t)r0 * D_ + col)       = v0;
            *(float2*)(g.C + (size_t)(r0 + 8) * D_ + col) = v1;
        }
    }
}

// ---------------- global-query attention: one block per (b, h), all 16 rows ----
// dyn smem: Qs 16x64 (4KB) + p 16x2048 (128KB) + invs
#define AG_OFF_P   4096
#define AG_OFF_I   (AG_OFF_P + 16 * S_ * 4)
#define AG_SMEM    (AG_OFF_I + 64)

__global__ __launch_bounds__(512) void attn_global(
    const float* __restrict__ Q, const float* __restrict__ K,
    const float* __restrict__ V, float* __restrict__ attn,
    __nv_bfloat16* __restrict__ ch, __nv_bfloat16* __restrict__ cl)
{
    extern __shared__ __align__(16) char sm[];
    float* Qs   = (float*)sm;
    float* p    = (float*)(sm + AG_OFF_P);
    float* invs = (float*)(sm + AG_OFF_I);

    const int h = blockIdx.x;
    const int b = blockIdx.y;
    const int tid = threadIdx.x;
    const int wid = tid >> 5;
    const int lane = tid & 31;

    // load 16 global Q rows (head slice)
    if (tid < 256) {
        const int r = tid >> 4, f4 = tid & 15;
        *(float4*)(Qs + r * 64 + f4 * 4) =
            *(const float4*)(Q + ((size_t)(b * S_ + r)) * D_ + h * HD_ + f4 * 4);
    }
    __syncthreads();

    // scores: thread j-stride 512, 16 rows per K-row load
    for (int j = tid; j < S_; j += 512) {
        const float* krow = K + ((size_t)(b * S_ + j)) * D_ + h * HD_;
        float acc[16];
#pragma unroll
        for (int r = 0; r < 16; ++r) acc[r] = 0.f;
#pragma unroll
        for (int d4 = 0; d4 < 16; ++d4) {
            float4 kv = *(const float4*)(krow + d4 * 4);
#pragma unroll
            for (int r = 0; r < 16; ++r) {
                float4 qv = *(const float4*)(Qs + r * 64 + d4 * 4);
                acc[r] = fmaf(kv.x, qv.x, acc[r]);
                acc[r] = fmaf(kv.y, qv.y, acc[r]);
                acc[r] = fmaf(kv.z, qv.z, acc[r]);
                acc[r] = fmaf(kv.w, qv.w, acc[r]);
            }
        }
#pragma unroll
        for (int r = 0; r < 16; ++r) p[r * S_ + j] = acc[r] * 0.125f;
    }
    __syncthreads();

    // softmax per row: warp w owns row w
    {
        float m = -1e30f;
        for (int j = lane; j < S_; j += 32) m = fmaxf(m, p[wid * S_ + j]);
#pragma unroll
        for (int o = 16; o; o >>= 1) m = fmaxf(m, __shfl_xor_sync(~0u, m, o));
        float sum = 0.f;
        for (int j = lane; j < S_; j += 32) {
            float e = __expf(p[wid * S_ + j] - m);
            p[wid * S_ + j] = e;
            sum += e;
        }
#pragma unroll
        for (int o = 16; o; o >>= 1) sum += __shfl_xor_sync(~0u, sum, o);
        const float inv = 1.f / sum;
        if (lane == 0) invs[wid] = inv;
        // write attn row (full, all nonzero for global rows)
        float* arow = attn + (((size_t)(b * H_ + h)) * S_ + wid) * S_;
        for (int j0 = lane * 4; j0 < S_; j0 += 128) {
            float4 o4;
            o4.x = p[wid * S_ + j0 + 0] * inv;
            o4.y = p[wid * S_ + j0 + 1] * inv;
            o4.z = p[wid * S_ + j0 + 2] * inv;
            o4.w = p[wid * S_ + j0 + 3] * inv;
            *(float4*)(arow + j0) = o4;
        }
    }
    __syncthreads();

    // ctx: thread (rg = tid/64 in 0..7, d = tid%64) handles rows rg, rg+8
    {
        const int d  = tid & 63;
        const int rg = tid >> 6;
        float a0 = 0.f, a1 = 0.f;
        const float* p0 = p + rg * S_;
        const float* p1 = p + (rg + 8) * S_;
        for (int j = 0; j < S_; ++j) {
            const float v = V[((size_t)(b * S_ + j)) * D_ + h * HD_ + d];
            a0 = fmaf(p0[j], v, a0);
            a1 = fmaf(p1[j], v, a1);
        }
        a0 *= invs[rg];
        a1 *= invs[rg + 8];
        __nv_bfloat16 h0, l0, h1, l1;
        f2bf_hilo(a0, h0, l0);
        f2bf_hilo(a1, h1, l1);
        const size_t o0 = ((size_t)(b * S_ + rg)) * D_ + h * HD_ + d;
        const size_t o1 = ((size_t)(b * S_ + rg + 8)) * D_ + h * HD_ + d;
        ch[o0] = h0; cl[o0] = l0;
        ch[o1] = h1; cl[o1] = l1;
    }
}

// ---------------- banded attention: 16 query rows per block -------------------
#define NC 96
#define KPAD 65
#define PPAD 97
#define BAND_OFF_Q  0
#define BAND_OFF_K  (16*64*4)
#define BAND_OFF_V  (BAND_OFF_K + NC*KPAD*4)
#define BAND_OFF_P  (BAND_OFF_V + NC*KPAD*4)
#define BAND_OFF_I  (BAND_OFF_P + 16*PPAD*4)
#define BAND_SMEM   (BAND_OFF_I + 64)

__global__ __launch_bounds__(256) void attn_band(
    const float* __restrict__ Q, const float* __restrict__ K,
    const float* __restrict__ V, float* __restrict__ attn,
    __nv_bfloat16* __restrict__ ch, __nv_bfloat16* __restrict__ cl)
{
    extern __shared__ __align__(16) char sm[];
    float* Qs = (float*)(sm + BAND_OFF_Q);
    float* Ks = (float*)(sm + BAND_OFF_K);
    float* Vs = (float*)(sm + BAND_OFF_V);
    float* p  = (float*)(sm + BAND_OFF_P);
    float* invs = (float*)(sm + BAND_OFF_I);

    const int i0 = GLB + blockIdx.x * 16;
    const int h  = blockIdx.y;
    const int b  = blockIdx.z;
    const int tid = threadIdx.x;

    const int blo = max(i0 - HALFW, GLB);
    const int bhi = min(i0 + 15 + HALFW, S_ - 1);
    const int nb  = bhi - blo + 1;

    {
        const int s = tid >> 4, f4 = tid & 15;
        float4 v = *(const float4*)(Q + ((size_t)(b * S_ + i0 + s)) * D_ + h * HD_ + f4 * 4);
        *(float4*)(Qs + s * 64 + f4 * 4) = v;
    }
    for (int task = tid; task < NC * 16; task += 256) {
        const int s = task >> 4, f4 = task & 15;
        float4 kv = make_float4(0.f, 0.f, 0.f, 0.f);
        float4 vv = make_float4(0.f, 0.f, 0.f, 0.f);
        int j = -1;
        if (s < GLB) j = s;
        else if (s - GLB < nb) j = blo + (s - GLB);
        if (j >= 0) {
            kv = *(const float4*)(K + ((size_t)(b * S_ + j)) * D_ + h * HD_ + f4 * 4);
            vv = *(const float4*)(V + ((size_t)(b * S_ + j)) * D_ + h * HD_ + f4 * 4);
        }
        float* kd = Ks + s * KPAD + f4 * 4;
        float* vd = Vs + s * KPAD + f4 * 4;
        kd[0] = kv.x; kd[1] = kv.y; kd[2] = kv.z; kd[3] = kv.w;
        vd[0] = vv.x; vd[1] = vv.y; vd[2] = vv.z; vd[3] = vv.w;
    }
    __syncthreads();

    for (int e = tid; e < 16 * NC; e += 256) {
        const int r = e / NC, c = e % NC;
        const int i = i0 + r;
        bool valid;
        if (c < GLB) valid = true;
        else {
            const int idx = c - GLB;
            const int j = blo + idx;
            valid = (idx < nb) && (j >= i - HALFW) && (j <= i + HALFW);
        }
        float s = 0.f;
        const float* kr = Ks + c * KPAD;
        const float* qr = Qs + r * 64;
#pragma unroll
        for (int d = 0; d < 64; ++d) s = fmaf(qr[d], kr[d], s);
        p[r * PPAD + c] = valid ? s * 0.125f : -1e30f;
    }
    __syncthreads();

    {
        const int w = tid >> 5, lane = tid & 31;
#pragma unroll
        for (int rr = 2 * w; rr <= 2 * w + 1; ++rr) {
            float m = -1e30f;
#pragma unroll
            for (int c = lane; c < NC; c += 32) m = fmaxf(m, p[rr * PPAD + c]);
#pragma unroll
            for (int o = 16; o; o >>= 1) m = fmaxf(m, __shfl_xor_sync(~0u, m, o));
            float sum = 0.f;
#pragma unroll
            for (int c = lane; c < NC; c += 32) {
                float e = __expf(p[rr * PPAD + c] - m);
                p[rr * PPAD + c] = e;   // invalid positions -> exp underflows to 0
                sum += e;
            }
#pragma unroll
            for (int o = 16; o; o >>= 1) sum += __shfl_xor_sync(~0u, sum, o);
            if (lane == 0) invs[rr] = 1.f / sum;
        }
    }
    __syncthreads();

    // write FULL attn rows (zeros included) — replaces the memset pass
    {
        const int w = tid >> 5, lane = tid & 31;
#pragma unroll
        for (int rr = 2 * w; rr <= 2 * w + 1; ++rr) {
            const float inv = invs[rr];
            const float* pr = p + rr * PPAD;
            float* arow = attn + (((size_t)(b * H_ + h)) * S_ + i0 + rr) * S_;
            for (int j0 = lane * 4; j0 < S_; j0 += 128) {
                float4 o4;
                float* op = &o4.x;
#pragma unroll
                for (int u = 0; u < 4; ++u) {
                    const int j = j0 + u;
                    float v = 0.f;
                    if (j < GLB)                    v = pr[j] * inv;
                    else if (j >= blo && j <= bhi)  v = pr[GLB + j - blo] * inv;
                    op[u] = v;
                }
                *(float4*)(arow + j0) = o4;
            }
        }
    }

    // ctx -> bf16 hi/lo directly
    {
        const int r = tid >> 4, dg = tid & 15;
        float a0 = 0.f, a1 = 0.f, a2 = 0.f, a3 = 0.f;
#pragma unroll 4
        for (int c = 0; c < NC; ++c) {
            const float wgt = p[r * PPAD + c];
            const float* vr = Vs + c * KPAD + dg * 4;
            a0 = fmaf(wgt, vr[0], a0); a1 = fmaf(wgt, vr[1], a1);
            a2 = fmaf(wgt, vr[2], a2); a3 = fmaf(wgt, vr[3], a3);
        }
        const float inv = invs[r];
        a0 *= inv; a1 *= inv; a2 *= inv; a3 *= inv;
        __nv_bfloat16 h0, h1, h2, h3, l0, l1, l2, l3;
        f2bf_hilo(a0, h0, l0); f2bf_hilo(a1, h1, l1);
        f2bf_hilo(a2, h2, l2); f2bf_hilo(a3, h3, l3);
        uint2 hp, lp;
        hp.x = (uint32_t)__bfloat16_as_ushort(h0) | ((uint32_t)__bfloat16_as_ushort(h1) << 16);
        hp.y = (uint32_t)__bfloat16_as_ushort(h2) | ((uint32_t)__bfloat16_as_ushort(h3) << 16);
        lp.x = (uint32_t)__bfloat16_as_ushort(l0) | ((uint32_t)__bfloat16_as_ushort(l1) << 16);
        lp.y = (uint32_t)__bfloat16_as_ushort(l2) | ((uint32_t)__bfloat16_as_ushort(l3) << 16);
        const size_t off = ((size_t)(b * S_ + i0 + r)) * D_ + h * HD_ + dg * 4;
        *(uint2*)(ch + off) = hp;
        *(uint2*)(cl + off) = lp;
    }
}

// ------------------------------- launch ---------------------------------------
extern "C" void kernel_launch(void* const* d_in, const int* in_sizes, int n_in,
                              void* d_out, int out_size)
{
    const float* query = (const float*)d_in[0];
    const float* key   = (const float*)d_in[1];
    const float* value = (const float*)d_in[2];
    const float* Wq = (const float*)d_in[3];
    const float* bq = (const float*)d_in[4];
    const float* Wk = (const float*)d_in[5];
    const float* bk = (const float*)d_in[6];
    const float* Wv = (const float*)d_in[7];
    const float* bv = (const float*)d_in[8];
    const float* Wo = (const float*)d_in[9];
    const float* bo = (const float*)d_in[10];

    float* out = (float*)d_out;

    float *Qp, *Kp, *Vp;
    cudaGetSymbolAddress((void**)&Qp, g_Q);
    cudaGetSymbolAddress((void**)&Kp, g_K);
    cudaGetSymbolAddress((void**)&Vp, g_V);

    __nv_bfloat16 *qh,*ql,*kh,*kl,*vh,*vl,*ch,*cl;
    __nv_bfloat16 *wqh,*wql,*wkh,*wkl,*wvh,*wvl,*woh,*wol;
    cudaGetSymbolAddress((void**)&qh, g_qh);  cudaGetSymbolAddress((void**)&ql, g_ql);
    cudaGetSymbolAddress((void**)&kh, g_kh);  cudaGetSymbolAddress((void**)&kl, g_kl);
    cudaGetSymbolAddress((void**)&vh, g_vh);  cudaGetSymbolAddress((void**)&vl, g_vl);
    cudaGetSymbolAddress((void**)&ch, g_ch);  cudaGetSymbolAddress((void**)&cl, g_cl);
    cudaGetSymbolAddress((void**)&wqh, g_wqh); cudaGetSymbolAddress((void**)&wql, g_wql);
    cudaGetSymbolAddress((void**)&wkh, g_wkh); cudaGetSymbolAddress((void**)&wkl, g_wkl);
    cudaGetSymbolAddress((void**)&wvh, g_wvh); cudaGetSymbolAddress((void**)&wvl, g_wvl);
    cudaGetSymbolAddress((void**)&woh, g_woh); cudaGetSymbolAddress((void**)&wol, g_wol);

    const size_t out_elems  = (size_t)B_ * S_ * D_;
    const size_t attn_elems = (size_t)B_ * H_ * S_ * S_;
    const bool write_attn = ((size_t)out_size >= out_elems + attn_elems);
    float* attn = write_attn ? (out + out_elems) : nullptr;

    static bool attr_done = false;
    if (!attr_done) {
        cudaFuncSetAttribute(gemm_mma, cudaFuncAttributeMaxDynamicSharedMemorySize, GEMM_SMEM);
        cudaFuncSetAttribute(attn_global, cudaFuncAttributeMaxDynamicSharedMemorySize, AG_SMEM);
        cudaFuncSetAttribute(attn_band, cudaFuncAttributeMaxDynamicSharedMemorySize, BAND_SMEM);
        attr_done = true;
    }

    {
        CvtArgs ci0{query, qh, ql}, ci1{key, kh, kl}, ci2{value, vh, vl};
        cvt_hilo<<<dim3(1024, 1, 3), 256>>>(ci0, ci1, ci2, ci2, MTOT * D_);
        CvtArgs cw0{Wq, wqh, wql}, cw1{Wk, wkh, wkl}, cw2{Wv, wvh, wvl}, cw3{Wo, woh, wol};
        cvt_hilo<<<dim3(512, 1, 4), 256>>>(cw0, cw1, cw2, cw3, D_ * D_);
    }

    GemmB bq_{qh, ql, wqh, wql, bq, Qp};
    GemmB bk_{kh, kl, wkh, wkl, bk, Kp};
    GemmB bv_{vh, vl, wvh, wvl, bv, Vp};

    dim3 gqkv(D_ / 128, MTOT / 128, 3);
    gemm_mma<<<gqkv, 256, GEMM_SMEM>>>(bq_, bk_, bv_);

    attn_global<<<dim3(H_, B_), 512, AG_SMEM>>>(Qp, Kp, Vp, attn, ch, cl);
    attn_band<<<dim3((S_ - GLB) / 16, H_, B_), 256, BAND_SMEM>>>(Qp, Kp, Vp, attn, ch, cl);

    GemmB bo_{ch, cl, woh, wol, bo, out};
    dim3 gout(D_ / 128, MTOT / 128, 1);
    gemm_mma<<<gout, 256, GEMM_SMEM>>>(bo_, bo_, bo_);
}

// round 6
// speedup vs baseline: 1.2351x; 1.2351x over previous
#include <cuda_runtime.h>
#include <cuda_bf16.h>
#include <math.h>
#include <stdint.h>

#define B_   2
#define S_   2048
#define D_   1024
#define H_   16
#define HD_  64
#define GLB  16
#define HALFW 32

#define MTOT (B_*S_)   // 4096

// ---------------- scratch ------------------------------------------------------
__device__ __align__(16) float g_Q[MTOT * D_];
__device__ __align__(16) float g_K[MTOT * D_];
__device__ __align__(16) float g_V[MTOT * D_];

__device__ __align__(16) __nv_bfloat16 g_qh[MTOT * D_], g_ql[MTOT * D_];
__device__ __align__(16) __nv_bfloat16 g_kh[MTOT * D_], g_kl[MTOT * D_];
__device__ __align__(16) __nv_bfloat16 g_vh[MTOT * D_], g_vl[MTOT * D_];
__device__ __align__(16) __nv_bfloat16 g_ch[MTOT * D_], g_cl[MTOT * D_];
__device__ __align__(16) __nv_bfloat16 g_wqh[D_ * D_], g_wql[D_ * D_];
__device__ __align__(16) __nv_bfloat16 g_wkh[D_ * D_], g_wkl[D_ * D_];
__device__ __align__(16) __nv_bfloat16 g_wvh[D_ * D_], g_wvl[D_ * D_];
__device__ __align__(16) __nv_bfloat16 g_woh[D_ * D_], g_wol[D_ * D_];

__device__ __forceinline__ uint32_t smem_u32(const void* p) {
    uint32_t a;
    asm("{ .reg .u64 t; cvta.to.shared.u64 t, %1; cvt.u32.u64 %0, t; }"
        : "=r"(a) : "l"(p));
    return a;
}
#define CPA16(daddr, gptr) \
    asm volatile("cp.async.ca.shared.global [%0], [%1], 16;" :: "r"(daddr), "l"(gptr))
#define CP_COMMIT() asm volatile("cp.async.commit_group;")
#define CP_WAIT1()  asm volatile("cp.async.wait_group 1;")

__device__ __forceinline__ void f2bf_hilo(float x, __nv_bfloat16& h, __nv_bfloat16& l) {
    h = __float2bfloat16_rn(x);
    l = __float2bfloat16_rn(x - __bfloat162float(h));
}

// ---------------- fp32 -> bf16 hi/lo pre-convert --------------------------------
struct CvtArgs { const float* in; __nv_bfloat16* h; __nv_bfloat16* l; };

__global__ __launch_bounds__(256) void cvt_hilo(
    CvtArgs c0, CvtArgs c1, CvtArgs c2, CvtArgs c3, int n)
{
    CvtArgs c = (blockIdx.z == 0) ? c0 : (blockIdx.z == 1) ? c1 :
                (blockIdx.z == 2) ? c2 : c3;
    const int stride = gridDim.x * blockDim.x * 4;
    for (int i = (blockIdx.x * blockDim.x + threadIdx.x) * 4; i < n; i += stride) {
        float4 v = *(const float4*)(c.in + i);
        __nv_bfloat16 h0, h1, h2, h3, l0, l1, l2, l3;
        f2bf_hilo(v.x, h0, l0); f2bf_hilo(v.y, h1, l1);
        f2bf_hilo(v.z, h2, l2); f2bf_hilo(v.w, h3, l3);
        uint2 hp, lp;
        hp.x = (uint32_t)__bfloat16_as_ushort(h0) | ((uint32_t)__bfloat16_as_ushort(h1) << 16);
        hp.y = (uint32_t)__bfloat16_as_ushort(h2) | ((uint32_t)__bfloat16_as_ushort(h3) << 16);
        lp.x = (uint32_t)__bfloat16_as_ushort(l0) | ((uint32_t)__bfloat16_as_ushort(l1) << 16);
        lp.y = (uint32_t)__bfloat16_as_ushort(l2) | ((uint32_t)__bfloat16_as_ushort(l3) << 16);
        *(uint2*)(c.h + i) = hp;
        *(uint2*)(c.l + i) = lp;
    }
}

// ---------------- HMMA GEMM (bf16x3, cp.async double-buffered) ------------------
struct GemmB {
    const __nv_bfloat16 *Ah, *Al, *Wh, *Wl;
    const float* bias;
    float* C;
};

#define SROW 40
#define TILE_BYTES (128 * SROW * 2)     // 10240
#define GEMM_SMEM  (2 * 4 * TILE_BYTES) // 81920

__device__ __forceinline__ uint32_t lds32(const char* base, int row, int k) {
    return *(const uint32_t*)(base + row * (SROW * 2) + k * 2);
}

__device__ __forceinline__ void mma16816(
    float& d0, float& d1, float& d2, float& d3,
    uint32_t a0, uint32_t a1, uint32_t a2, uint32_t a3,
    uint32_t b0, uint32_t b1)
{
    asm volatile(
        "mma.sync.aligned.m16n8k16.row.col.f32.bf16.bf16.f32 "
        "{%0,%1,%2,%3}, {%4,%5,%6,%7}, {%8,%9}, {%0,%1,%2,%3};"
        : "+f"(d0), "+f"(d1), "+f"(d2), "+f"(d3)
        : "r"(a0), "r"(a1), "r"(a2), "r"(a3), "r"(b0), "r"(b1));
}

__global__ __launch_bounds__(256) void gemm_mma(GemmB g0, GemmB g1, GemmB g2)
{
    GemmB g = (blockIdx.z == 0) ? g0 : ((blockIdx.z == 1) ? g1 : g2);

    extern __shared__ __align__(16) char dsm[];
    const uint32_t sb = smem_u32(dsm);

    const int tid  = threadIdx.x;
    const int wid  = tid >> 5;
    const int lane = tid & 31;
    const int bm = blockIdx.y * 128;
    const int bn = blockIdx.x * 128;
    const int warp_m = (wid & 1) * 64;
    const int warp_n = (wid >> 1) * 32;

    const int grow = tid >> 1;
    const int gk   = (tid & 1) << 4;
    const __nv_bfloat16* pAh = g.Ah + (size_t)(bm + grow) * D_ + gk;
    const __nv_bfloat16* pAl = g.Al + (size_t)(bm + grow) * D_ + gk;
    const __nv_bfloat16* pBh = g.Wh + (size_t)(bn + grow) * D_ + gk;
    const __nv_bfloat16* pBl = g.Wl + (size_t)(bn + grow) * D_ + gk;
    const uint32_t soff = (uint32_t)(grow * (SROW * 2) + gk * 2);

    float acc[4][4][4];
#pragma unroll
    for (int mt = 0; mt < 4; mt++)
#pragma unroll
        for (int nt = 0; nt < 4; nt++)
#pragma unroll
            for (int q = 0; q < 4; q++) acc[mt][nt][q] = 0.f;

    const int fr = lane >> 2;
    const int fk = (lane & 3) << 1;

#define ISSUE(chunk, stage) do {                                            \
        const int _off = (chunk) * 32;                                      \
        const uint32_t _s = sb + (stage) * 4 * TILE_BYTES + soff;           \
        CPA16(_s + 0 * TILE_BYTES,      pAh + _off);                        \
        CPA16(_s + 0 * TILE_BYTES + 16, pAh + _off + 8);                    \
        CPA16(_s + 1 * TILE_BYTES,      pAl + _off);                        \
        CPA16(_s + 1 * TILE_BYTES + 16, pAl + _off + 8);                    \
        CPA16(_s + 2 * TILE_BYTES,      pBh + _off);                        \
        CPA16(_s + 2 * TILE_BYTES + 16, pBh + _off + 8);                    \
        CPA16(_s + 3 * TILE_BYTES,      pBl + _off);                        \
        CPA16(_s + 3 * TILE_BYTES + 16, pBl + _off + 8);                    \
    } while (0)

    ISSUE(0, 0); CP_COMMIT();
    ISSUE(1, 1); CP_COMMIT();

    for (int c = 0; c < 32; ++c) {
        CP_WAIT1();
        __syncthreads();
        const char* base = dsm + (c & 1) * 4 * TILE_BYTES;
        const char* sAh = base;
        const char* sAl = base + TILE_BYTES;
        const char* sBh = base + 2 * TILE_BYTES;
        const char* sBl = base + 3 * TILE_BYTES;

#pragma unroll
        for (int ks = 0; ks < 2; ++ks) {
            const int kk = ks * 16 + fk;
            uint32_t ah[4][4];
#pragma unroll
            for (int mt = 0; mt < 4; mt++) {
                const int r = warp_m + mt * 16 + fr;
                ah[mt][0] = lds32(sAh, r,     kk);
                ah[mt][1] = lds32(sAh, r + 8, kk);
                ah[mt][2] = lds32(sAh, r,     kk + 8);
                ah[mt][3] = lds32(sAh, r + 8, kk + 8);
            }
            uint32_t bh[4][2];
#pragma unroll
            for (int nt = 0; nt < 4; nt++) {
                const int n = warp_n + nt * 8 + fr;
                bh[nt][0] = lds32(sBh, n, kk);
                bh[nt][1] = lds32(sBh, n, kk + 8);
            }
#pragma unroll
            for (int mt = 0; mt < 4; mt++)
#pragma unroll
                for (int nt = 0; nt < 4; nt++)
                    mma16816(acc[mt][nt][0], acc[mt][nt][1], acc[mt][nt][2], acc[mt][nt][3],
                             ah[mt][0], ah[mt][1], ah[mt][2], ah[mt][3],
                             bh[nt][0], bh[nt][1]);
#pragma unroll
            for (int mt = 0; mt < 4; mt++) {
                const int r = warp_m + mt * 16 + fr;
                uint32_t al0 = lds32(sAl, r,     kk);
                uint32_t al1 = lds32(sAl, r + 8, kk);
                uint32_t al2 = lds32(sAl, r,     kk + 8);
                uint32_t al3 = lds32(sAl, r + 8, kk + 8);
#pragma unroll
                for (int nt = 0; nt < 4; nt++)
                    mma16816(acc[mt][nt][0], acc[mt][nt][1], acc[mt][nt][2], acc[mt][nt][3],
                             al0, al1, al2, al3, bh[nt][0], bh[nt][1]);
            }
#pragma unroll
            for (int nt = 0; nt < 4; nt++) {
                const int n = warp_n + nt * 8 + fr;
                uint32_t bl0 = lds32(sBl, n, kk);
                uint32_t bl1 = lds32(sBl, n, kk + 8);
#pragma unroll
                for (int mt = 0; mt < 4; mt++)
                    mma16816(acc[mt][nt][0], acc[mt][nt][1], acc[mt][nt][2], acc[mt][nt][3],
                             ah[mt][0], ah[mt][1], ah[mt][2], ah[mt][3],
                             bl0, bl1);
            }
        }
        __syncthreads();
        if (c + 2 < 32) ISSUE(c + 2, c & 1);
        CP_COMMIT();
    }
#undef ISSUE

#pragma unroll
    for (int mt = 0; mt < 4; mt++) {
        const int r0 = bm + warp_m + mt * 16 + fr;
#pragma unroll
        for (int nt = 0; nt < 4; nt++) {
            const int col = bn + warp_n + nt * 8 + fk;
            const float b0 = g.bias[col], b1 = g.bias[col + 1];
            float2 v0 = make_float2(acc[mt][nt][0] + b0, acc[mt][nt][1] + b1);
            float2 v1 = make_float2(acc[mt][nt][2] + b0, acc[mt][nt][3] + b1);
            *(float2*)(g.C + (size_t)r0 * D_ + col)       = v0;
            *(float2*)(g.C + (size_t)(r0 + 8) * D_ + col) = v1;
        }
    }
}

// ---------------- global-query attention: one block per (b, h, row) -----------
// 256 threads; ctx uses 4-way j-split x 4-deep unroll (16 loads in flight).
__global__ __launch_bounds__(256) void attn_global(
    const float* __restrict__ Q, const float* __restrict__ K,
    const float* __restrict__ V, float* __restrict__ attn,
    __nv_bfloat16* __restrict__ ch, __nv_bfloat16* __restrict__ cl)
{
    const int i = blockIdx.x;     // 0..15 (global row)
    const int h = blockIdx.y;
    const int b = blockIdx.z;
    const int tid = threadIdx.x;

    __shared__ __align__(16) float qs[HD_];
    __shared__ float p[S_];
    __shared__ float red[8];
    __shared__ float sb;
    __shared__ float cpart[4][HD_];

    const float* qrow = Q + ((size_t)(b * S_ + i)) * D_ + h * HD_;
    if (tid < HD_) qs[tid] = qrow[tid];
    __syncthreads();

    // ---- scores: 8 dots per thread ----
    float lmax = -1e30f;
    for (int j = tid; j < S_; j += 256) {
        const float* krow = K + ((size_t)(b * S_ + j)) * D_ + h * HD_;
        float s = 0.f;
#pragma unroll
        for (int d = 0; d < HD_; d += 4) {
            float4 kv = *(const float4*)(krow + d);
            float4 qv = *(const float4*)(qs + d);
            s = fmaf(qv.x, kv.x, s); s = fmaf(qv.y, kv.y, s);
            s = fmaf(qv.z, kv.z, s); s = fmaf(qv.w, kv.w, s);
        }
        s *= 0.125f;
        p[j] = s;
        lmax = fmaxf(lmax, s);
    }
#pragma unroll
    for (int o = 16; o; o >>= 1) lmax = fmaxf(lmax, __shfl_xor_sync(~0u, lmax, o));
    if ((tid & 31) == 0) red[tid >> 5] = lmax;
    __syncthreads();
    if (tid == 0) {
        float m = red[0];
#pragma unroll
        for (int w = 1; w < 8; ++w) m = fmaxf(m, red[w]);
        sb = m;
    }
    __syncthreads();
    const float m = sb;
    __syncthreads();

    float lsum = 0.f;
    for (int j = tid; j < S_; j += 256) { float e = __expf(p[j] - m); p[j] = e; lsum += e; }
#pragma unroll
    for (int o = 16; o; o >>= 1) lsum += __shfl_xor_sync(~0u, lsum, o);
    if ((tid & 31) == 0) red[tid >> 5] = lsum;
    __syncthreads();
    if (tid == 0) {
        float s = red[0];
#pragma unroll
        for (int w = 1; w < 8; ++w) s += red[w];
        sb = 1.f / s;
    }
    __syncthreads();
    const float inv = sb;

    // ---- write full attn row ----
    {
        float* arow = attn + (((size_t)(b * H_ + h)) * S_ + i) * S_;
        for (int j0 = tid * 4; j0 < S_; j0 += 256 * 4) {
            float4 o4;
            o4.x = p[j0 + 0] * inv; o4.y = p[j0 + 1] * inv;
            o4.z = p[j0 + 2] * inv; o4.w = p[j0 + 3] * inv;
            *(float4*)(arow + j0) = o4;
        }
    }

    // ---- ctx: 4-way j-split, 4 independent accumulators each ----
    {
        const int d = tid & 63;
        const int q = tid >> 6;        // 0..3
        const float* vp = V + ((size_t)(b * S_)) * D_ + h * HD_ + d;
        float a0 = 0.f, a1 = 0.f, a2 = 0.f, a3 = 0.f;
        const int j0 = q * 512;
#pragma unroll 4
        for (int j = j0; j < j0 + 512; j += 4) {
            a0 = fmaf(p[j + 0], vp[(size_t)(j + 0) * D_], a0);
            a1 = fmaf(p[j + 1], vp[(size_t)(j + 1) * D_], a1);
            a2 = fmaf(p[j + 2], vp[(size_t)(j + 2) * D_], a2);
            a3 = fmaf(p[j + 3], vp[(size_t)(j + 3) * D_], a3);
        }
        cpart[q][d] = (a0 + a1) + (a2 + a3);
        __syncthreads();
        if (tid < HD_) {
            float s = ((cpart[0][tid] + cpart[1][tid]) +
                       (cpart[2][tid] + cpart[3][tid])) * inv;
            __nv_bfloat16 hh, ll;
            f2bf_hilo(s, hh, ll);
            const size_t off = ((size_t)(b * S_ + i)) * D_ + h * HD_ + tid;
            ch[off] = hh; cl[off] = ll;
        }
    }
}

// ---------------- banded attention: 16 query rows per block -------------------
#define NC 96
#define KPAD 65
#define PPAD 97
#define BAND_OFF_Q  0
#define BAND_OFF_K  (16*64*4)
#define BAND_OFF_V  (BAND_OFF_K + NC*KPAD*4)
#define BAND_OFF_P  (BAND_OFF_V + NC*KPAD*4)
#define BAND_OFF_I  (BAND_OFF_P + 16*PPAD*4)
#define BAND_SMEM   (BAND_OFF_I + 64)

__global__ __launch_bounds__(256) void attn_band(
    const float* __restrict__ Q, const float* __restrict__ K,
    const float* __restrict__ V, float* __restrict__ attn,
    __nv_bfloat16* __restrict__ ch, __nv_bfloat16* __restrict__ cl)
{
    extern __shared__ __align__(16) char sm[];
    float* Qs = (float*)(sm + BAND_OFF_Q);
    float* Ks = (float*)(sm + BAND_OFF_K);
    float* Vs = (float*)(sm + BAND_OFF_V);
    float* p  = (float*)(sm + BAND_OFF_P);
    float* invs = (float*)(sm + BAND_OFF_I);

    const int i0 = GLB + blockIdx.x * 16;
    const int h  = blockIdx.y;
    const int b  = blockIdx.z;
    const int tid = threadIdx.x;

    const int blo = max(i0 - HALFW, GLB);
    const int bhi = min(i0 + 15 + HALFW, S_ - 1);
    const int nb  = bhi - blo + 1;

    {
        const int s = tid >> 4, f4 = tid & 15;
        float4 v = *(const float4*)(Q + ((size_t)(b * S_ + i0 + s)) * D_ + h * HD_ + f4 * 4);
        *(float4*)(Qs + s * 64 + f4 * 4) = v;
    }
    for (int task = tid; task < NC * 16; task += 256) {
        const int s = task >> 4, f4 = task & 15;
        float4 kv = make_float4(0.f, 0.f, 0.f, 0.f);
        float4 vv = make_float4(0.f, 0.f, 0.f, 0.f);
        int j = -1;
        if (s < GLB) j = s;
        else if (s - GLB < nb) j = blo + (s - GLB);
        if (j >= 0) {
            kv = *(const float4*)(K + ((size_t)(b * S_ + j)) * D_ + h * HD_ + f4 * 4);
            vv = *(const float4*)(V + ((size_t)(b * S_ + j)) * D_ + h * HD_ + f4 * 4);
        }
        float* kd = Ks + s * KPAD + f4 * 4;
        float* vd = Vs + s * KPAD + f4 * 4;
        kd[0] = kv.x; kd[1] = kv.y; kd[2] = kv.z; kd[3] = kv.w;
        vd[0] = vv.x; vd[1] = vv.y; vd[2] = vv.z; vd[3] = vv.w;
    }
    __syncthreads();

    for (int e = tid; e < 16 * NC; e += 256) {
        const int r = e / NC, c = e % NC;
        const int i = i0 + r;
        bool valid;
        if (c < GLB) valid = true;
        else {
            const int idx = c - GLB;
            const int j = blo + idx;
            valid = (idx < nb) && (j >= i - HALFW) && (j <= i + HALFW);
        }
        float s = 0.f;
        const float* kr = Ks + c * KPAD;
        const float* qr = Qs + r * 64;
#pragma unroll
        for (int d = 0; d < 64; ++d) s = fmaf(qr[d], kr[d], s);
        p[r * PPAD + c] = valid ? s * 0.125f : -1e30f;
    }
    __syncthreads();

    {
        const int w = tid >> 5, lane = tid & 31;
#pragma unroll
        for (int rr = 2 * w; rr <= 2 * w + 1; ++rr) {
            float m = -1e30f;
#pragma unroll
            for (int c = lane; c < NC; c += 32) m = fmaxf(m, p[rr * PPAD + c]);
#pragma unroll
            for (int o = 16; o; o >>= 1) m = fmaxf(m, __shfl_xor_sync(~0u, m, o));
            float sum = 0.f;
#pragma unroll
            for (int c = lane; c < NC; c += 32) {
                float e = __expf(p[rr * PPAD + c] - m);
                p[rr * PPAD + c] = e;
                sum += e;
            }
#pragma unroll
            for (int o = 16; o; o >>= 1) sum += __shfl_xor_sync(~0u, sum, o);
            if (lane == 0) invs[rr] = 1.f / sum;
        }
    }
    __syncthreads();

    // write FULL attn rows (zeros included) — no memset pass
    {
        const int w = tid >> 5, lane = tid & 31;
#pragma unroll
        for (int rr = 2 * w; rr <= 2 * w + 1; ++rr) {
            const float inv = invs[rr];
            const float* pr = p + rr * PPAD;
            float* arow = attn + (((size_t)(b * H_ + h)) * S_ + i0 + rr) * S_;
            for (int j0 = lane * 4; j0 < S_; j0 += 128) {
                float4 o4;
                float* op = &o4.x;
#pragma unroll
                for (int u = 0; u < 4; ++u) {
                    const int j = j0 + u;
                    float v = 0.f;
                    if (j < GLB)                    v = pr[j] * inv;
                    else if (j >= blo && j <= bhi)  v = pr[GLB + j - blo] * inv;
                    op[u] = v;
                }
                *(float4*)(arow + j0) = o4;
            }
        }
    }

    // ctx -> bf16 hi/lo directly
    {
        const int r = tid >> 4, dg = tid & 15;
        float a0 = 0.f, a1 = 0.f, a2 = 0.f, a3 = 0.f;
#pragma unroll 4
        for (int c = 0; c < NC; ++c) {
            const float wgt = p[r * PPAD + c];
            const float* vr = Vs + c * KPAD + dg * 4;
            a0 = fmaf(wgt, vr[0], a0); a1 = fmaf(wgt, vr[1], a1);
            a2 = fmaf(wgt, vr[2], a2); a3 = fmaf(wgt, vr[3], a3);
        }
        const float inv = invs[r];
        a0 *= inv; a1 *= inv; a2 *= inv; a3 *= inv;
        __nv_bfloat16 h0, h1, h2, h3, l0, l1, l2, l3;
        f2bf_hilo(a0, h0, l0); f2bf_hilo(a1, h1, l1);
        f2bf_hilo(a2, h2, l2); f2bf_hilo(a3, h3, l3);
        uint2 hp, lp;
        hp.x = (uint32_t)__bfloat16_as_ushort(h0) | ((uint32_t)__bfloat16_as_ushort(h1) << 16);
        hp.y = (uint32_t)__bfloat16_as_ushort(h2) | ((uint32_t)__bfloat16_as_ushort(h3) << 16);
        lp.x = (uint32_t)__bfloat16_as_ushort(l0) | ((uint32_t)__bfloat16_as_ushort(l1) << 16);
        lp.y = (uint32_t)__bfloat16_as_ushort(l2) | ((uint32_t)__bfloat16_as_ushort(l3) << 16);
        const size_t off = ((size_t)(b * S_ + i0 + r)) * D_ + h * HD_ + dg * 4;
        *(uint2*)(ch + off) = hp;
        *(uint2*)(cl + off) = lp;
    }
}

// ------------------------------- launch ---------------------------------------
extern "C" void kernel_launch(void* const* d_in, const int* in_sizes, int n_in,
                              void* d_out, int out_size)
{
    const float* query = (const float*)d_in[0];
    const float* key   = (const float*)d_in[1];
    const float* value = (const float*)d_in[2];
    const float* Wq = (const float*)d_in[3];
    const float* bq = (const float*)d_in[4];
    const float* Wk = (const float*)d_in[5];
    const float* bk = (const float*)d_in[6];
    const float* Wv = (const float*)d_in[7];
    const float* bv = (const float*)d_in[8];
    const float* Wo = (const float*)d_in[9];
    const float* bo = (const float*)d_in[10];

    float* out = (float*)d_out;

    float *Qp, *Kp, *Vp;
    cudaGetSymbolAddress((void**)&Qp, g_Q);
    cudaGetSymbolAddress((void**)&Kp, g_K);
    cudaGetSymbolAddress((void**)&Vp, g_V);

    __nv_bfloat16 *qh,*ql,*kh,*kl,*vh,*vl,*ch,*cl;
    __nv_bfloat16 *wqh,*wql,*wkh,*wkl,*wvh,*wvl,*woh,*wol;
    cudaGetSymbolAddress((void**)&qh, g_qh);  cudaGetSymbolAddress((void**)&ql, g_ql);
    cudaGetSymbolAddress((void**)&kh, g_kh);  cudaGetSymbolAddress((void**)&kl, g_kl);
    cudaGetSymbolAddress((void**)&vh, g_vh);  cudaGetSymbolAddress((void**)&vl, g_vl);
    cudaGetSymbolAddress((void**)&ch, g_ch);  cudaGetSymbolAddress((void**)&cl, g_cl);
    cudaGetSymbolAddress((void**)&wqh, g_wqh); cudaGetSymbolAddress((void**)&wql, g_wql);
    cudaGetSymbolAddress((void**)&wkh, g_wkh); cudaGetSymbolAddress((void**)&wkl, g_wkl);
    cudaGetSymbolAddress((void**)&wvh, g_wvh); cudaGetSymbolAddress((void**)&wvl, g_wvl);
    cudaGetSymbolAddress((void**)&woh, g_woh); cudaGetSymbolAddress((void**)&wol, g_wol);

    const size_t out_elems  = (size_t)B_ * S_ * D_;
    const size_t attn_elems = (size_t)B_ * H_ * S_ * S_;
    const bool write_attn = ((size_t)out_size >= out_elems + attn_elems);
    float* attn = write_attn ? (out + out_elems) : nullptr;

    static bool attr_done = false;
    if (!attr_done) {
        cudaFuncSetAttribute(gemm_mma, cudaFuncAttributeMaxDynamicSharedMemorySize, GEMM_SMEM);
        cudaFuncSetAttribute(attn_band, cudaFuncAttributeMaxDynamicSharedMemorySize, BAND_SMEM);
        attr_done = true;
    }

    {
        CvtArgs ci0{query, qh, ql}, ci1{key, kh, kl}, ci2{value, vh, vl};
        cvt_hilo<<<dim3(1024, 1, 3), 256>>>(ci0, ci1, ci2, ci2, MTOT * D_);
        CvtArgs cw0{Wq, wqh, wql}, cw1{Wk, wkh, wkl}, cw2{Wv, wvh, wvl}, cw3{Wo, woh, wol};
        cvt_hilo<<<dim3(512, 1, 4), 256>>>(cw0, cw1, cw2, cw3, D_ * D_);
    }

    GemmB bq_{qh, ql, wqh, wql, bq, Qp};
    GemmB bk_{kh, kl, wkh, wkl, bk, Kp};
    GemmB bv_{vh, vl, wvh, wvl, bv, Vp};

    dim3 gqkv(D_ / 128, MTOT / 128, 3);
    gemm_mma<<<gqkv, 256, GEMM_SMEM>>>(bq_, bk_, bv_);

    attn_global<<<dim3(GLB, H_, B_), 256>>>(Qp, Kp, Vp, attn, ch, cl);
    attn_band<<<dim3((S_ - GLB) / 16, H_, B_), 256, BAND_SMEM>>>(Qp, Kp, Vp, attn, ch, cl);

    GemmB bo_{ch, cl, woh, wol, bo, out};
    dim3 gout(D_ / 128, MTOT / 128, 1);
    gemm_mma<<<gout, 256, GEMM_SMEM>>>(bo_, bo_, bo_);
}

// round 7
// speedup vs baseline: 1.3169x; 1.0663x over previous
#include <cuda_runtime.h>
#include <cuda_bf16.h>
#include <math.h>
#include <stdint.h>

#define B_   2
#define S_   2048
#define D_   1024
#define H_   16
#define HD_  64
#define GLB  16
#define HALFW 32

#define MTOT (B_*S_)   // 4096

// ---------------- scratch ------------------------------------------------------
__device__ __align__(16) float g_Q[MTOT * D_];
__device__ __align__(16) float g_K[MTOT * D_];
__device__ __align__(16) float g_V[MTOT * D_];

__device__ __align__(16) __nv_bfloat16 g_qh[MTOT * D_], g_ql[MTOT * D_];
__device__ __align__(16) __nv_bfloat16 g_kh[MTOT * D_], g_kl[MTOT * D_];
__device__ __align__(16) __nv_bfloat16 g_vh[MTOT * D_], g_vl[MTOT * D_];
__device__ __align__(16) __nv_bfloat16 g_ch[MTOT * D_], g_cl[MTOT * D_];
__device__ __align__(16) __nv_bfloat16 g_wqh[D_ * D_], g_wql[D_ * D_];
__device__ __align__(16) __nv_bfloat16 g_wkh[D_ * D_], g_wkl[D_ * D_];
__device__ __align__(16) __nv_bfloat16 g_wvh[D_ * D_], g_wvl[D_ * D_];
__device__ __align__(16) __nv_bfloat16 g_woh[D_ * D_], g_wol[D_ * D_];

__device__ __forceinline__ uint32_t smem_u32(const void* p) {
    uint32_t a;
    asm("{ .reg .u64 t; cvta.to.shared.u64 t, %1; cvt.u32.u64 %0, t; }"
        : "=r"(a) : "l"(p));
    return a;
}
#define CPA16(daddr, gptr) \
    asm volatile("cp.async.ca.shared.global [%0], [%1], 16;" :: "r"(daddr), "l"(gptr))
#define CP_COMMIT() asm volatile("cp.async.commit_group;")
#define CP_WAIT1()  asm volatile("cp.async.wait_group 1;")

__device__ __forceinline__ void f2bf_hilo(float x, __nv_bfloat16& h, __nv_bfloat16& l) {
    h = __float2bfloat16_rn(x);
    l = __float2bfloat16_rn(x - __bfloat162float(h));
}

// ---------------- fp32 -> bf16 hi/lo pre-convert --------------------------------
struct CvtArgs { const float* in; __nv_bfloat16* h; __nv_bfloat16* l; };

__global__ __launch_bounds__(256) void cvt_hilo(
    CvtArgs c0, CvtArgs c1, CvtArgs c2, CvtArgs c3, int n)
{
    CvtArgs c = (blockIdx.z == 0) ? c0 : (blockIdx.z == 1) ? c1 :
                (blockIdx.z == 2) ? c2 : c3;
    const int stride = gridDim.x * blockDim.x * 4;
    for (int i = (blockIdx.x * blockDim.x + threadIdx.x) * 4; i < n; i += stride) {
        float4 v = *(const float4*)(c.in + i);
        __nv_bfloat16 h0, h1, h2, h3, l0, l1, l2, l3;
        f2bf_hilo(v.x, h0, l0); f2bf_hilo(v.y, h1, l1);
        f2bf_hilo(v.z, h2, l2); f2bf_hilo(v.w, h3, l3);
        uint2 hp, lp;
        hp.x = (uint32_t)__bfloat16_as_ushort(h0) | ((uint32_t)__bfloat16_as_ushort(h1) << 16);
        hp.y = (uint32_t)__bfloat16_as_ushort(h2) | ((uint32_t)__bfloat16_as_ushort(h3) << 16);
        lp.x = (uint32_t)__bfloat16_as_ushort(l0) | ((uint32_t)__bfloat16_as_ushort(l1) << 16);
        lp.y = (uint32_t)__bfloat16_as_ushort(l2) | ((uint32_t)__bfloat16_as_ushort(l3) << 16);
        *(uint2*)(c.h + i) = hp;
        *(uint2*)(c.l + i) = lp;
    }
}

// ---------------- HMMA GEMM (bf16x3, cp.async double-buffered) ------------------
struct GemmB {
    const __nv_bfloat16 *Ah, *Al, *Wh, *Wl;
    const float* bias;
    float* C;
};

#define SROW 40
#define TILE_BYTES (128 * SROW * 2)     // 10240
#define GEMM_SMEM  (2 * 4 * TILE_BYTES) // 81920

__device__ __forceinline__ uint32_t lds32(const char* base, int row, int k) {
    return *(const uint32_t*)(base + row * (SROW * 2) + k * 2);
}

__device__ __forceinline__ void mma16816(
    float& d0, float& d1, float& d2, float& d3,
    uint32_t a0, uint32_t a1, uint32_t a2, uint32_t a3,
    uint32_t b0, uint32_t b1)
{
    asm volatile(
        "mma.sync.aligned.m16n8k16.row.col.f32.bf16.bf16.f32 "
        "{%0,%1,%2,%3}, {%4,%5,%6,%7}, {%8,%9}, {%0,%1,%2,%3};"
        : "+f"(d0), "+f"(d1), "+f"(d2), "+f"(d3)
        : "r"(a0), "r"(a1), "r"(a2), "r"(a3), "r"(b0), "r"(b1));
}

__global__ __launch_bounds__(256) void gemm_mma(GemmB g0, GemmB g1, GemmB g2)
{
    GemmB g = (blockIdx.z == 0) ? g0 : ((blockIdx.z == 1) ? g1 : g2);

    extern __shared__ __align__(16) char dsm[];
    const uint32_t sb = smem_u32(dsm);

    const int tid  = threadIdx.x;
    const int wid  = tid >> 5;
    const int lane = tid & 31;
    const int bm = blockIdx.y * 128;
    const int bn = blockIdx.x * 128;
    const int warp_m = (wid & 1) * 64;
    const int warp_n = (wid >> 1) * 32;

    const int grow = tid >> 1;
    const int gk   = (tid & 1) << 4;
    const __nv_bfloat16* pAh = g.Ah + (size_t)(bm + grow) * D_ + gk;
    const __nv_bfloat16* pAl = g.Al + (size_t)(bm + grow) * D_ + gk;
    const __nv_bfloat16* pBh = g.Wh + (size_t)(bn + grow) * D_ + gk;
    const __nv_bfloat16* pBl = g.Wl + (size_t)(bn + grow) * D_ + gk;
    const uint32_t soff = (uint32_t)(grow * (SROW * 2) + gk * 2);

    float acc[4][4][4];
#pragma unroll
    for (int mt = 0; mt < 4; mt++)
#pragma unroll
        for (int nt = 0; nt < 4; nt++)
#pragma unroll
            for (int q = 0; q < 4; q++) acc[mt][nt][q] = 0.f;

    const int fr = lane >> 2;
    const int fk = (lane & 3) << 1;

#define ISSUE(chunk, stage) do {                                            \
        const int _off = (chunk) * 32;                                      \
        const uint32_t _s = sb + (stage) * 4 * TILE_BYTES + soff;           \
        CPA16(_s + 0 * TILE_BYTES,      pAh + _off);                        \
        CPA16(_s + 0 * TILE_BYTES + 16, pAh + _off + 8);                    \
        CPA16(_s + 1 * TILE_BYTES,      pAl + _off);                        \
        CPA16(_s + 1 * TILE_BYTES + 16, pAl + _off + 8);                    \
        CPA16(_s + 2 * TILE_BYTES,      pBh + _off);                        \
        CPA16(_s + 2 * TILE_BYTES + 16, pBh + _off + 8);                    \
        CPA16(_s + 3 * TILE_BYTES,      pBl + _off);                        \
        CPA16(_s + 3 * TILE_BYTES + 16, pBl + _off + 8);                    \
    } while (0)

    ISSUE(0, 0); CP_COMMIT();
    ISSUE(1, 1); CP_COMMIT();

    for (int c = 0; c < 32; ++c) {
        CP_WAIT1();
        __syncthreads();
        const char* base = dsm + (c & 1) * 4 * TILE_BYTES;
        const char* sAh = base;
        const char* sAl = base + TILE_BYTES;
        const char* sBh = base + 2 * TILE_BYTES;
        const char* sBl = base + 3 * TILE_BYTES;

#pragma unroll
        for (int ks = 0; ks < 2; ++ks) {
            const int kk = ks * 16 + fk;
            uint32_t ah[4][4];
#pragma unroll
            for (int mt = 0; mt < 4; mt++) {
                const int r = warp_m + mt * 16 + fr;
                ah[mt][0] = lds32(sAh, r,     kk);
                ah[mt][1] = lds32(sAh, r + 8, kk);
                ah[mt][2] = lds32(sAh, r,     kk + 8);
                ah[mt][3] = lds32(sAh, r + 8, kk + 8);
            }
            uint32_t bh[4][2];
#pragma unroll
            for (int nt = 0; nt < 4; nt++) {
                const int n = warp_n + nt * 8 + fr;
                bh[nt][0] = lds32(sBh, n, kk);
                bh[nt][1] = lds32(sBh, n, kk + 8);
            }
#pragma unroll
            for (int mt = 0; mt < 4; mt++)
#pragma unroll
                for (int nt = 0; nt < 4; nt++)
                    mma16816(acc[mt][nt][0], acc[mt][nt][1], acc[mt][nt][2], acc[mt][nt][3],
                             ah[mt][0], ah[mt][1], ah[mt][2], ah[mt][3],
                             bh[nt][0], bh[nt][1]);
#pragma unroll
            for (int mt = 0; mt < 4; mt++) {
                const int r = warp_m + mt * 16 + fr;
                uint32_t al0 = lds32(sAl, r,     kk);
                uint32_t al1 = lds32(sAl, r + 8, kk);
                uint32_t al2 = lds32(sAl, r,     kk + 8);
                uint32_t al3 = lds32(sAl, r + 8, kk + 8);
#pragma unroll
                for (int nt = 0; nt < 4; nt++)
                    mma16816(acc[mt][nt][0], acc[mt][nt][1], acc[mt][nt][2], acc[mt][nt][3],
                             al0, al1, al2, al3, bh[nt][0], bh[nt][1]);
            }
#pragma unroll
            for (int nt = 0; nt < 4; nt++) {
                const int n = warp_n + nt * 8 + fr;
                uint32_t bl0 = lds32(sBl, n, kk);
                uint32_t bl1 = lds32(sBl, n, kk + 8);
#pragma unroll
                for (int mt = 0; mt < 4; mt++)
                    mma16816(acc[mt][nt][0], acc[mt][nt][1], acc[mt][nt][2], acc[mt][nt][3],
                             ah[mt][0], ah[mt][1], ah[mt][2], ah[mt][3],
                             bl0, bl1);
            }
        }
        __syncthreads();
        if (c + 2 < 32) ISSUE(c + 2, c & 1);
        CP_COMMIT();
    }
#undef ISSUE

#pragma unroll
    for (int mt = 0; mt < 4; mt++) {
        const int r0 = bm + warp_m + mt * 16 + fr;
#pragma unroll
        for (int nt = 0; nt < 4; nt++) {
            const int col = bn + warp_n + nt * 8 + fk;
            const float b0 = g.bias[col], b1 = g.bias[col + 1];
            float2 v0 = make_float2(acc[mt][nt][0] + b0, acc[mt][nt][1] + b1);
            float2 v1 = make_float2(acc[mt][nt][2] + b0, acc[mt][nt][3] + b1);
            *(float2*)(g.C + (size_t)r0 * D_ + col)       = v0;
            *(float2*)(g.C + (size_t)(r0 + 8) * D_ + col) = v1;
        }
    }
}

// ---------------- global-query attention: one block per (b, h, row) -----------
// 256 threads. Scores: half-warp per K row (coalesced 256B). ctx: warp per
// j-chunk, lane covers 2 dims via float2 (coalesced 256B rows, 2 in flight).
__global__ __launch_bounds__(256) void attn_global(
    const float* __restrict__ Q, const float* __restrict__ K,
    const float* __restrict__ V, float* __restrict__ attn,
    __nv_bfloat16* __restrict__ ch, __nv_bfloat16* __restrict__ cl)
{
    const int i = blockIdx.x;     // 0..15 (global row)
    const int h = blockIdx.y;
    const int b = blockIdx.z;
    const int tid = threadIdx.x;
    const int wid = tid >> 5;
    const int lane = tid & 31;

    __shared__ __align__(16) float qs[HD_];
    __shared__ float p[S_];
    __shared__ float red[8];
    __shared__ float sb;
    __shared__ __align__(16) float cpart[8][HD_];

    const float* qrow = Q + ((size_t)(b * S_ + i)) * D_ + h * HD_;
    if (tid < HD_) qs[tid] = qrow[tid];
    __syncthreads();

    // ---- scores: half-warp (16 lanes) per K row, coalesced ----
    const int hw = lane >> 4;          // 0/1
    const int t  = lane & 15;          // dim group
    const float4 qv = *(const float4*)(qs + t * 4);
    float lmax = -1e30f;
    const float* kbase = K + ((size_t)(b * S_)) * D_ + h * HD_ + t * 4;
    for (int j = wid * 2 + hw; j < S_; j += 16) {
        float4 kv = *(const float4*)(kbase + (size_t)j * D_);
        float s = kv.x * qv.x + kv.y * qv.y + kv.z * qv.z + kv.w * qv.w;
#pragma unroll
        for (int o = 8; o; o >>= 1) s += __shfl_xor_sync(~0u, s, o);
        s *= 0.125f;
        if (t == 0) p[j] = s;
        lmax = fmaxf(lmax, s);
    }
#pragma unroll
    for (int o = 16; o; o >>= 1) lmax = fmaxf(lmax, __shfl_xor_sync(~0u, lmax, o));
    if (lane == 0) red[wid] = lmax;
    __syncthreads();
    if (tid == 0) {
        float m = red[0];
#pragma unroll
        for (int w = 1; w < 8; ++w) m = fmaxf(m, red[w]);
        sb = m;
    }
    __syncthreads();
    const float m = sb;
    __syncthreads();

    float lsum = 0.f;
    for (int j = tid; j < S_; j += 256) { float e = __expf(p[j] - m); p[j] = e; lsum += e; }
#pragma unroll
    for (int o = 16; o; o >>= 1) lsum += __shfl_xor_sync(~0u, lsum, o);
    if (lane == 0) red[wid] = lsum;
    __syncthreads();
    if (tid == 0) {
        float s = red[0];
#pragma unroll
        for (int w = 1; w < 8; ++w) s += red[w];
        sb = 1.f / s;
    }
    __syncthreads();
    const float inv = sb;

    // ---- write full attn row ----
    {
        float* arow = attn + (((size_t)(b * H_ + h)) * S_ + i) * S_;
        for (int j0 = tid * 4; j0 < S_; j0 += 256 * 4) {
            float4 o4;
            o4.x = p[j0 + 0] * inv; o4.y = p[j0 + 1] * inv;
            o4.z = p[j0 + 2] * inv; o4.w = p[j0 + 3] * inv;
            *(float4*)(arow + j0) = o4;
        }
    }

    // ---- ctx: warp per j-chunk of 256; lane covers dims (2*lane, 2*lane+1) ----
    {
        const float* vbase = V + ((size_t)(b * S_)) * D_ + h * HD_ + lane * 2;
        float a0 = 0.f, a1 = 0.f, b0 = 0.f, b1 = 0.f;
        const int j0 = wid * 256;
#pragma unroll 4
        for (int j = j0; j < j0 + 256; j += 2) {
            float2 v0 = *(const float2*)(vbase + (size_t)j * D_);
            float2 v1 = *(const float2*)(vbase + (size_t)(j + 1) * D_);
            const float p0 = p[j], p1 = p[j + 1];
            a0 = fmaf(p0, v0.x, a0); a1 = fmaf(p0, v0.y, a1);
            b0 = fmaf(p1, v1.x, b0); b1 = fmaf(p1, v1.y, b1);
        }
        cpart[wid][lane * 2]     = a0 + b0;
        cpart[wid][lane * 2 + 1] = a1 + b1;
        __syncthreads();
        if (tid < HD_) {
            float s = 0.f;
#pragma unroll
            for (int w = 0; w < 8; ++w) s += cpart[w][tid];
            s *= inv;
            __nv_bfloat16 hh, ll;
            f2bf_hilo(s, hh, ll);
            const size_t off = ((size_t)(b * S_ + i)) * D_ + h * HD_ + tid;
            ch[off] = hh; cl[off] = ll;
        }
    }
}

// ---------------- banded attention: 16 query rows per block -------------------
#define NC 96
#define KPAD 65
#define PPAD 97
#define BAND_OFF_Q  0
#define BAND_OFF_K  (16*64*4)
#define BAND_OFF_V  (BAND_OFF_K + NC*KPAD*4)
#define BAND_OFF_P  (BAND_OFF_V + NC*KPAD*4)
#define BAND_OFF_I  (BAND_OFF_P + 16*PPAD*4)
#define BAND_SMEM   (BAND_OFF_I + 64)

__global__ __launch_bounds__(256) void attn_band(
    const float* __restrict__ Q, const float* __restrict__ K,
    const float* __restrict__ V, float* __restrict__ attn,
    __nv_bfloat16* __restrict__ ch, __nv_bfloat16* __restrict__ cl)
{
    extern __shared__ __align__(16) char sm[];
    float* Qs = (float*)(sm + BAND_OFF_Q);
    float* Ks = (float*)(sm + BAND_OFF_K);
    float* Vs = (float*)(sm + BAND_OFF_V);
    float* p  = (float*)(sm + BAND_OFF_P);
    float* invs = (float*)(sm + BAND_OFF_I);

    const int i0 = GLB + blockIdx.x * 16;
    const int h  = blockIdx.y;
    const int b  = blockIdx.z;
    const int tid = threadIdx.x;

    const int blo = max(i0 - HALFW, GLB);
    const int bhi = min(i0 + 15 + HALFW, S_ - 1);
    const int nb  = bhi - blo + 1;

    {
        const int s = tid >> 4, f4 = tid & 15;
        float4 v = *(const float4*)(Q + ((size_t)(b * S_ + i0 + s)) * D_ + h * HD_ + f4 * 4);
        *(float4*)(Qs + s * 64 + f4 * 4) = v;
    }
    for (int task = tid; task < NC * 16; task += 256) {
        const int s = task >> 4, f4 = task & 15;
        float4 kv = make_float4(0.f, 0.f, 0.f, 0.f);
        float4 vv = make_float4(0.f, 0.f, 0.f, 0.f);
        int j = -1;
        if (s < GLB) j = s;
        else if (s - GLB < nb) j = blo + (s - GLB);
        if (j >= 0) {
            kv = *(const float4*)(K + ((size_t)(b * S_ + j)) * D_ + h * HD_ + f4 * 4);
            vv = *(const float4*)(V + ((size_t)(b * S_ + j)) * D_ + h * HD_ + f4 * 4);
        }
        float* kd = Ks + s * KPAD + f4 * 4;
        float* vd = Vs + s * KPAD + f4 * 4;
        kd[0] = kv.x; kd[1] = kv.y; kd[2] = kv.z; kd[3] = kv.w;
        vd[0] = vv.x; vd[1] = vv.y; vd[2] = vv.z; vd[3] = vv.w;
    }
    __syncthreads();

    for (int e = tid; e < 16 * NC; e += 256) {
        const int r = e / NC, c = e % NC;
        const int i = i0 + r;
        bool valid;
        if (c < GLB) valid = true;
        else {
            const int idx = c - GLB;
            const int j = blo + idx;
            valid = (idx < nb) && (j >= i - HALFW) && (j <= i + HALFW);
        }
        float s = 0.f;
        const float* kr = Ks + c * KPAD;
        const float* qr = Qs + r * 64;
#pragma unroll
        for (int d = 0; d < 64; ++d) s = fmaf(qr[d], kr[d], s);
        p[r * PPAD + c] = valid ? s * 0.125f : -1e30f;
    }
    __syncthreads();

    {
        const int w = tid >> 5, lane = tid & 31;
#pragma unroll
        for (int rr = 2 * w; rr <= 2 * w + 1; ++rr) {
            float m = -1e30f;
#pragma unroll
            for (int c = lane; c < NC; c += 32) m = fmaxf(m, p[rr * PPAD + c]);
#pragma unroll
            for (int o = 16; o; o >>= 1) m = fmaxf(m, __shfl_xor_sync(~0u, m, o));
            float sum = 0.f;
#pragma unroll
            for (int c = lane; c < NC; c += 32) {
                float e = __expf(p[rr * PPAD + c] - m);
                p[rr * PPAD + c] = e;
                sum += e;
            }
#pragma unroll
            for (int o = 16; o; o >>= 1) sum += __shfl_xor_sync(~0u, sum, o);
            if (lane == 0) invs[rr] = 1.f / sum;
        }
    }
    __syncthreads();

    {
        const int w = tid >> 5, lane = tid & 31;
#pragma unroll
        for (int rr = 2 * w; rr <= 2 * w + 1; ++rr) {
            const float inv = invs[rr];
            const float* pr = p + rr * PPAD;
            float* arow = attn + (((size_t)(b * H_ + h)) * S_ + i0 + rr) * S_;
            for (int j0 = lane * 4; j0 < S_; j0 += 128) {
                float4 o4;
                float* op = &o4.x;
#pragma unroll
                for (int u = 0; u < 4; ++u) {
                    const int j = j0 + u;
                    float v = 0.f;
                    if (j < GLB)                    v = pr[j] * inv;
                    else if (j >= blo && j <= bhi)  v = pr[GLB + j - blo] * inv;
                    op[u] = v;
                }
                *(float4*)(arow + j0) = o4;
            }
        }
    }

    {
        const int r = tid >> 4, dg = tid & 15;
        float a0 = 0.f, a1 = 0.f, a2 = 0.f, a3 = 0.f;
#pragma unroll 4
        for (int c = 0; c < NC; ++c) {
            const float wgt = p[r * PPAD + c];
            const float* vr = Vs + c * KPAD + dg * 4;
            a0 = fmaf(wgt, vr[0], a0); a1 = fmaf(wgt, vr[1], a1);
            a2 = fmaf(wgt, vr[2], a2); a3 = fmaf(wgt, vr[3], a3);
        }
        const float inv = invs[r];
        a0 *= inv; a1 *= inv; a2 *= inv; a3 *= inv;
        __nv_bfloat16 h0, h1, h2, h3, l0, l1, l2, l3;
        f2bf_hilo(a0, h0, l0); f2bf_hilo(a1, h1, l1);
        f2bf_hilo(a2, h2, l2); f2bf_hilo(a3, h3, l3);
        uint2 hp, lp;
        hp.x = (uint32_t)__bfloat16_as_ushort(h0) | ((uint32_t)__bfloat16_as_ushort(h1) << 16);
        hp.y = (uint32_t)__bfloat16_as_ushort(h2) | ((uint32_t)__bfloat16_as_ushort(h3) << 16);
        lp.x = (uint32_t)__bfloat16_as_ushort(l0) | ((uint32_t)__bfloat16_as_ushort(l1) << 16);
        lp.y = (uint32_t)__bfloat16_as_ushort(l2) | ((uint32_t)__bfloat16_as_ushort(l3) << 16);
        const size_t off = ((size_t)(b * S_ + i0 + r)) * D_ + h * HD_ + dg * 4;
        *(uint2*)(ch + off) = hp;
        *(uint2*)(cl + off) = lp;
    }
}

// ------------------------------- launch ---------------------------------------
extern "C" void kernel_launch(void* const* d_in, const int* in_sizes, int n_in,
                              void* d_out, int out_size)
{
    const float* query = (const float*)d_in[0];
    const float* key   = (const float*)d_in[1];
    const float* value = (const float*)d_in[2];
    const float* Wq = (const float*)d_in[3];
    const float* bq = (const float*)d_in[4];
    const float* Wk = (const float*)d_in[5];
    const float* bk = (const float*)d_in[6];
    const float* Wv = (const float*)d_in[7];
    const float* bv = (const float*)d_in[8];
    const float* Wo = (const float*)d_in[9];
    const float* bo = (const float*)d_in[10];

    float* out = (float*)d_out;

    float *Qp, *Kp, *Vp;
    cudaGetSymbolAddress((void**)&Qp, g_Q);
    cudaGetSymbolAddress((void**)&Kp, g_K);
    cudaGetSymbolAddress((void**)&Vp, g_V);

    __nv_bfloat16 *qh,*ql,*kh,*kl,*vh,*vl,*ch,*cl;
    __nv_bfloat16 *wqh,*wql,*wkh,*wkl,*wvh,*wvl,*woh,*wol;
    cudaGetSymbolAddress((void**)&qh, g_qh);  cudaGetSymbolAddress((void**)&ql, g_ql);
    cudaGetSymbolAddress((void**)&kh, g_kh);  cudaGetSymbolAddress((void**)&kl, g_kl);
    cudaGetSymbolAddress((void**)&vh, g_vh);  cudaGetSymbolAddress((void**)&vl, g_vl);
    cudaGetSymbolAddress((void**)&ch, g_ch);  cudaGetSymbolAddress((void**)&cl, g_cl);
    cudaGetSymbolAddress((void**)&wqh, g_wqh); cudaGetSymbolAddress((void**)&wql, g_wql);
    cudaGetSymbolAddress((void**)&wkh, g_wkh); cudaGetSymbolAddress((void**)&wkl, g_wkl);
    cudaGetSymbolAddress((void**)&wvh, g_wvh); cudaGetSymbolAddress((void**)&wvl, g_wvl);
    cudaGetSymbolAddress((void**)&woh, g_woh); cudaGetSymbolAddress((void**)&wol, g_wol);

    const size_t out_elems  = (size_t)B_ * S_ * D_;
    const size_t attn_elems = (size_t)B_ * H_ * S_ * S_;
    const bool write_attn = ((size_t)out_size >= out_elems + attn_elems);
    float* attn = write_attn ? (out + out_elems) : nullptr;

    static bool attr_done = false;
    if (!attr_done) {
        cudaFuncSetAttribute(gemm_mma, cudaFuncAttributeMaxDynamicSharedMemorySize, GEMM_SMEM);
        cudaFuncSetAttribute(attn_band, cudaFuncAttributeMaxDynamicSharedMemorySize, BAND_SMEM);
        attr_done = true;
    }

    {
        CvtArgs ci0{query, qh, ql}, ci1{key, kh, kl}, ci2{value, vh, vl};
        cvt_hilo<<<dim3(1024, 1, 3), 256>>>(ci0, ci1, ci2, ci2, MTOT * D_);
        CvtArgs cw0{Wq, wqh, wql}, cw1{Wk, wkh, wkl}, cw2{Wv, wvh, wvl}, cw3{Wo, woh, wol};
        cvt_hilo<<<dim3(512, 1, 4), 256>>>(cw0, cw1, cw2, cw3, D_ * D_);
    }

    GemmB bq_{qh, ql, wqh, wql, bq, Qp};
    GemmB bk_{kh, kl, wkh, wkl, bk, Kp};
    GemmB bv_{vh, vl, wvh, wvl, bv, Vp};

    dim3 gqkv(D_ / 128, MTOT / 128, 3);
    gemm_mma<<<gqkv, 256, GEMM_SMEM>>>(bq_, bk_, bv_);

    attn_global<<<dim3(GLB, H_, B_), 256>>>(Qp, Kp, Vp, attn, ch, cl);
    attn_band<<<dim3((S_ - GLB) / 16, H_, B_), 256, BAND_SMEM>>>(Qp, Kp, Vp, attn, ch, cl);

    GemmB bo_{ch, cl, woh, wol, bo, out};
    dim3 gout(D_ / 128, MTOT / 128, 1);
    gemm_mma<<<gout, 256, GEMM_SMEM>>>(bo_, bo_, bo_);
}

// round 8
// speedup vs baseline: 1.4709x; 1.1169x over previous
#include <cuda_runtime.h>
#include <cuda_bf16.h>
#include <math.h>
#include <stdint.h>

#define B_   2
#define S_   2048
#define D_   1024
#define H_   16
#define HD_  64
#define GLB  16
#define HALFW 32

#define MTOT (B_*S_)   // 4096

// ---------------- scratch ------------------------------------------------------
__device__ __align__(16) float g_Q[MTOT * D_];
__device__ __align__(16) float g_K[MTOT * D_];
__device__ __align__(16) float g_V[MTOT * D_];

__device__ __align__(16) __nv_bfloat16 g_qh[MTOT * D_], g_ql[MTOT * D_];
__device__ __align__(16) __nv_bfloat16 g_kh[MTOT * D_], g_kl[MTOT * D_];
__device__ __align__(16) __nv_bfloat16 g_vh[MTOT * D_], g_vl[MTOT * D_];
__device__ __align__(16) __nv_bfloat16 g_ch[MTOT * D_], g_cl[MTOT * D_];
__device__ __align__(16) __nv_bfloat16 g_wqh[D_ * D_], g_wql[D_ * D_];
__device__ __align__(16) __nv_bfloat16 g_wkh[D_ * D_], g_wkl[D_ * D_];
__device__ __align__(16) __nv_bfloat16 g_wvh[D_ * D_], g_wvl[D_ * D_];
__device__ __align__(16) __nv_bfloat16 g_woh[D_ * D_], g_wol[D_ * D_];

__device__ __forceinline__ uint32_t smem_u32(const void* p) {
    uint32_t a;
    asm("{ .reg .u64 t; cvta.to.shared.u64 t, %1; cvt.u32.u64 %0, t; }"
        : "=r"(a) : "l"(p));
    return a;
}
#define CPA16(daddr, gptr) \
    asm volatile("cp.async.ca.shared.global [%0], [%1], 16;" :: "r"(daddr), "l"(gptr))
#define CP_COMMIT() asm volatile("cp.async.commit_group;")
#define CP_WAIT1()  asm volatile("cp.async.wait_group 1;")

#define LDSM4(r0, r1, r2, r3, a) \
    asm volatile("ldmatrix.sync.aligned.m8n8.x4.shared.b16 {%0,%1,%2,%3}, [%4];" \
                 : "=r"(r0), "=r"(r1), "=r"(r2), "=r"(r3) : "r"(a))

__device__ __forceinline__ void f2bf_hilo(float x, __nv_bfloat16& h, __nv_bfloat16& l) {
    h = __float2bfloat16_rn(x);
    l = __float2bfloat16_rn(x - __bfloat162float(h));
}

// ---------------- fp32 -> bf16 hi/lo pre-convert --------------------------------
struct CvtArgs { const float* in; __nv_bfloat16* h; __nv_bfloat16* l; };

__global__ __launch_bounds__(256) void cvt_hilo(
    CvtArgs c0, CvtArgs c1, CvtArgs c2, CvtArgs c3, int n)
{
    CvtArgs c = (blockIdx.z == 0) ? c0 : (blockIdx.z == 1) ? c1 :
                (blockIdx.z == 2) ? c2 : c3;
    const int stride = gridDim.x * blockDim.x * 4;
    for (int i = (blockIdx.x * blockDim.x + threadIdx.x) * 4; i < n; i += stride) {
        float4 v = *(const float4*)(c.in + i);
        __nv_bfloat16 h0, h1, h2, h3, l0, l1, l2, l3;
        f2bf_hilo(v.x, h0, l0); f2bf_hilo(v.y, h1, l1);
        f2bf_hilo(v.z, h2, l2); f2bf_hilo(v.w, h3, l3);
        uint2 hp, lp;
        hp.x = (uint32_t)__bfloat16_as_ushort(h0) | ((uint32_t)__bfloat16_as_ushort(h1) << 16);
        hp.y = (uint32_t)__bfloat16_as_ushort(h2) | ((uint32_t)__bfloat16_as_ushort(h3) << 16);
        lp.x = (uint32_t)__bfloat16_as_ushort(l0) | ((uint32_t)__bfloat16_as_ushort(l1) << 16);
        lp.y = (uint32_t)__bfloat16_as_ushort(l2) | ((uint32_t)__bfloat16_as_ushort(l3) << 16);
        *(uint2*)(c.h + i) = hp;
        *(uint2*)(c.l + i) = lp;
    }
}

// ---------------- HMMA GEMM (bf16x3, cp.async double-buffered, ldmatrix) --------
struct GemmB {
    const __nv_bfloat16 *Ah, *Al, *Wh, *Wl;
    const float* bias;
    float* C;
};

#define SROW 40
#define SROWB (SROW * 2)                // 80 bytes
#define TILE_BYTES (128 * SROWB)        // 10240
#define GEMM_SMEM  (2 * 4 * TILE_BYTES) // 81920

__device__ __forceinline__ void mma16816(
    float& d0, float& d1, float& d2, float& d3,
    uint32_t a0, uint32_t a1, uint32_t a2, uint32_t a3,
    uint32_t b0, uint32_t b1)
{
    asm volatile(
        "mma.sync.aligned.m16n8k16.row.col.f32.bf16.bf16.f32 "
        "{%0,%1,%2,%3}, {%4,%5,%6,%7}, {%8,%9}, {%0,%1,%2,%3};"
        : "+f"(d0), "+f"(d1), "+f"(d2), "+f"(d3)
        : "r"(a0), "r"(a1), "r"(a2), "r"(a3), "r"(b0), "r"(b1));
}

__global__ __launch_bounds__(256) void gemm_mma(GemmB g0, GemmB g1, GemmB g2)
{
    GemmB g = (blockIdx.z == 0) ? g0 : ((blockIdx.z == 1) ? g1 : g2);

    extern __shared__ __align__(16) char dsm[];
    const uint32_t sb = smem_u32(dsm);

    const int tid  = threadIdx.x;
    const int wid  = tid >> 5;
    const int lane = tid & 31;
    const int bm = blockIdx.y * 128;
    const int bn = blockIdx.x * 128;
    const int warp_m = (wid & 1) * 64;
    const int warp_n = (wid >> 1) * 32;

    const int grow = tid >> 1;
    const int gk   = (tid & 1) << 4;
    const __nv_bfloat16* pAh = g.Ah + (size_t)(bm + grow) * D_ + gk;
    const __nv_bfloat16* pAl = g.Al + (size_t)(bm + grow) * D_ + gk;
    const __nv_bfloat16* pBh = g.Wh + (size_t)(bn + grow) * D_ + gk;
    const __nv_bfloat16* pBl = g.Wl + (size_t)(bn + grow) * D_ + gk;
    const uint32_t soff = (uint32_t)(grow * SROWB + gk * 2);

    float acc[4][4][4];
#pragma unroll
    for (int mt = 0; mt < 4; mt++)
#pragma unroll
        for (int nt = 0; nt < 4; nt++)
#pragma unroll
            for (int q = 0; q < 4; q++) acc[mt][nt][q] = 0.f;

    const int fr = lane >> 2;
    const int fk = (lane & 3) << 1;

    // ldmatrix lane->address components
    const int aRow  = lane & 15;               // row within 16-row tile
    const int aKoff = (lane >> 4) << 3;        // 0 or 8 (k-half)
    const int bRowO = (lane & 7) + ((lane >> 4) << 3);   // row within 16-n pair
    const int bKoff = ((lane >> 3) & 1) << 3;  // 0 or 8

#define ISSUE(chunk, stage) do {                                            \
        const int _off = (chunk) * 32;                                      \
        const uint32_t _s = sb + (stage) * 4 * TILE_BYTES + soff;           \
        CPA16(_s + 0 * TILE_BYTES,      pAh + _off);                        \
        CPA16(_s + 0 * TILE_BYTES + 16, pAh + _off + 8);                    \
        CPA16(_s + 1 * TILE_BYTES,      pAl + _off);                        \
        CPA16(_s + 1 * TILE_BYTES + 16, pAl + _off + 8);                    \
        CPA16(_s + 2 * TILE_BYTES,      pBh + _off);                        \
        CPA16(_s + 2 * TILE_BYTES + 16, pBh + _off + 8);                    \
        CPA16(_s + 3 * TILE_BYTES,      pBl + _off);                        \
        CPA16(_s + 3 * TILE_BYTES + 16, pBl + _off + 8);                    \
    } while (0)

    ISSUE(0, 0); CP_COMMIT();
    ISSUE(1, 1); CP_COMMIT();

    for (int c = 0; c < 32; ++c) {
        CP_WAIT1();
        __syncthreads();
        const uint32_t base = sb + (c & 1) * 4 * TILE_BYTES;
        const uint32_t sAh = base;
        const uint32_t sAl = base + TILE_BYTES;
        const uint32_t sBh = base + 2 * TILE_BYTES;
        const uint32_t sBl = base + 3 * TILE_BYTES;

#pragma unroll
        for (int ks = 0; ks < 2; ++ks) {
            const int kk = ks * 16;
            const uint32_t aByte = (uint32_t)((kk + aKoff) * 2);
            const uint32_t bByte = (uint32_t)((kk + bKoff) * 2);

            // A-hi fragments: one LDSM.x4 per 16-row tile
            uint32_t ah[4][4];
#pragma unroll
            for (int mt = 0; mt < 4; mt++) {
                const uint32_t addr = sAh + (uint32_t)(warp_m + mt * 16 + aRow) * SROWB + aByte;
                LDSM4(ah[mt][0], ah[mt][1], ah[mt][2], ah[mt][3], addr);
            }
            // B-hi fragments: one LDSM.x4 per pair of 8-n tiles
            uint32_t bh[4][2];
#pragma unroll
            for (int p = 0; p < 2; p++) {
                const uint32_t addr = sBh + (uint32_t)(warp_n + p * 16 + bRowO) * SROWB + bByte;
                LDSM4(bh[2 * p][0], bh[2 * p][1], bh[2 * p + 1][0], bh[2 * p + 1][1], addr);
            }
            // pass 1: Ah x Bh
#pragma unroll
            for (int mt = 0; mt < 4; mt++)
#pragma unroll
                for (int nt = 0; nt < 4; nt++)
                    mma16816(acc[mt][nt][0], acc[mt][nt][1], acc[mt][nt][2], acc[mt][nt][3],
                             ah[mt][0], ah[mt][1], ah[mt][2], ah[mt][3],
                             bh[nt][0], bh[nt][1]);
            // pass 2: Al x Bh
#pragma unroll
            for (int mt = 0; mt < 4; mt++) {
                uint32_t al0, al1, al2, al3;
                const uint32_t addr = sAl + (uint32_t)(warp_m + mt * 16 + aRow) * SROWB + aByte;
                LDSM4(al0, al1, al2, al3, addr);
#pragma unroll
                for (int nt = 0; nt < 4; nt++)
                    mma16816(acc[mt][nt][0], acc[mt][nt][1], acc[mt][nt][2], acc[mt][nt][3],
                             al0, al1, al2, al3, bh[nt][0], bh[nt][1]);
            }
            // pass 3: Ah x Bl
#pragma unroll
            for (int p = 0; p < 2; p++) {
                uint32_t bl00, bl01, bl10, bl11;
                const uint32_t addr = sBl + (uint32_t)(warp_n + p * 16 + bRowO) * SROWB + bByte;
                LDSM4(bl00, bl01, bl10, bl11, addr);
#pragma unroll
                for (int mt = 0; mt < 4; mt++) {
                    mma16816(acc[mt][2 * p][0], acc[mt][2 * p][1], acc[mt][2 * p][2], acc[mt][2 * p][3],
                             ah[mt][0], ah[mt][1], ah[mt][2], ah[mt][3], bl00, bl01);
                    mma16816(acc[mt][2 * p + 1][0], acc[mt][2 * p + 1][1], acc[mt][2 * p + 1][2], acc[mt][2 * p + 1][3],
                             ah[mt][0], ah[mt][1], ah[mt][2], ah[mt][3], bl10, bl11);
                }
            }
        }
        __syncthreads();
        if (c + 2 < 32) ISSUE(c + 2, c & 1);
        CP_COMMIT();
    }
#undef ISSUE

#pragma unroll
    for (int mt = 0; mt < 4; mt++) {
        const int r0 = bm + warp_m + mt * 16 + fr;
#pragma unroll
        for (int nt = 0; nt < 4; nt++) {
            const int col = bn + warp_n + nt * 8 + fk;
            const float b0 = g.bias[col], b1 = g.bias[col + 1];
            float2 v0 = make_float2(acc[mt][nt][0] + b0, acc[mt][nt][1] + b1);
            float2 v1 = make_float2(acc[mt][nt][2] + b0, acc[mt][nt][3] + b1);
            *(float2*)(g.C + (size_t)r0 * D_ + col)       = v0;
            *(float2*)(g.C + (size_t)(r0 + 8) * D_ + col) = v1;
        }
    }
}

// ---------------- global-query attention: one block per (b, h, row) -----------
__global__ __launch_bounds__(256) void attn_global(
    const float* __restrict__ Q, const float* __restrict__ K,
    const float* __restrict__ V, float* __restrict__ attn,
    __nv_bfloat16* __restrict__ ch, __nv_bfloat16* __restrict__ cl)
{
    const int i = blockIdx.x;
    const int h = blockIdx.y;
    const int b = blockIdx.z;
    const int tid = threadIdx.x;
    const int wid = tid >> 5;
    const int lane = tid & 31;

    __shared__ __align__(16) float qs[HD_];
    __shared__ float p[S_];
    __shared__ float red[8];
    __shared__ float sb;
    __shared__ __align__(16) float cpart[8][HD_];

    const float* qrow = Q + ((size_t)(b * S_ + i)) * D_ + h * HD_;
    if (tid < HD_) qs[tid] = qrow[tid];
    __syncthreads();

    const int hw = lane >> 4;
    const int t  = lane & 15;
    const float4 qv = *(const float4*)(qs + t * 4);
    float lmax = -1e30f;
    const float* kbase = K + ((size_t)(b * S_)) * D_ + h * HD_ + t * 4;
    for (int j = wid * 2 + hw; j < S_; j += 16) {
        float4 kv = *(const float4*)(kbase + (size_t)j * D_);
        float s = kv.x * qv.x + kv.y * qv.y + kv.z * qv.z + kv.w * qv.w;
#pragma unroll
        for (int o = 8; o; o >>= 1) s += __shfl_xor_sync(~0u, s, o);
        s *= 0.125f;
        if (t == 0) p[j] = s;
        lmax = fmaxf(lmax, s);
    }
#pragma unroll
    for (int o = 16; o; o >>= 1) lmax = fmaxf(lmax, __shfl_xor_sync(~0u, lmax, o));
    if (lane == 0) red[wid] = lmax;
    __syncthreads();
    if (tid == 0) {
        float m = red[0];
#pragma unroll
        for (int w = 1; w < 8; ++w) m = fmaxf(m, red[w]);
        sb = m;
    }
    __syncthreads();
    const float m = sb;
    __syncthreads();

    float lsum = 0.f;
    for (int j = tid; j < S_; j += 256) { float e = __expf(p[j] - m); p[j] = e; lsum += e; }
#pragma unroll
    for (int o = 16; o; o >>= 1) lsum += __shfl_xor_sync(~0u, lsum, o);
    if (lane == 0) red[wid] = lsum;
    __syncthreads();
    if (tid == 0) {
        float s = red[0];
#pragma unroll
        for (int w = 1; w < 8; ++w) s += red[w];
        sb = 1.f / s;
    }
    __syncthreads();
    const float inv = sb;

    {
        float* arow = attn + (((size_t)(b * H_ + h)) * S_ + i) * S_;
        for (int j0 = tid * 4; j0 < S_; j0 += 256 * 4) {
            float4 o4;
            o4.x = p[j0 + 0] * inv; o4.y = p[j0 + 1] * inv;
            o4.z = p[j0 + 2] * inv; o4.w = p[j0 + 3] * inv;
            *(float4*)(arow + j0) = o4;
        }
    }

    {
        const float* vbase = V + ((size_t)(b * S_)) * D_ + h * HD_ + lane * 2;
        float a0 = 0.f, a1 = 0.f, b0 = 0.f, b1 = 0.f;
        const int j0 = wid * 256;
#pragma unroll 4
        for (int j = j0; j < j0 + 256; j += 2) {
            float2 v0 = *(const float2*)(vbase + (size_t)j * D_);
            float2 v1 = *(const float2*)(vbase + (size_t)(j + 1) * D_);
            const float p0 = p[j], p1 = p[j + 1];
            a0 = fmaf(p0, v0.x, a0); a1 = fmaf(p0, v0.y, a1);
            b0 = fmaf(p1, v1.x, b0); b1 = fmaf(p1, v1.y, b1);
        }
        cpart[wid][lane * 2]     = a0 + b0;
        cpart[wid][lane * 2 + 1] = a1 + b1;
        __syncthreads();
        if (tid < HD_) {
            float s = 0.f;
#pragma unroll
            for (int w = 0; w < 8; ++w) s += cpart[w][tid];
            s *= inv;
            __nv_bfloat16 hh, ll;
            f2bf_hilo(s, hh, ll);
            const size_t off = ((size_t)(b * S_ + i)) * D_ + h * HD_ + tid;
            ch[off] = hh; cl[off] = ll;
        }
    }
}

// ---------------- banded attention: 16 query rows per block -------------------
#define NC 96
#define KPAD 65
#define PPAD 97
#define BAND_OFF_Q  0
#define BAND_OFF_K  (16*64*4)
#define BAND_OFF_V  (BAND_OFF_K + NC*KPAD*4)
#define BAND_OFF_P  (BAND_OFF_V + NC*KPAD*4)
#define BAND_OFF_I  (BAND_OFF_P + 16*PPAD*4)
#define BAND_SMEM   (BAND_OFF_I + 64)

__global__ __launch_bounds__(256) void attn_band(
    const float* __restrict__ Q, const float* __restrict__ K,
    const float* __restrict__ V, float* __restrict__ attn,
    __nv_bfloat16* __restrict__ ch, __nv_bfloat16* __restrict__ cl)
{
    extern __shared__ __align__(16) char sm[];
    float* Qs = (float*)(sm + BAND_OFF_Q);
    float* Ks = (float*)(sm + BAND_OFF_K);
    float* Vs = (float*)(sm + BAND_OFF_V);
    float* p  = (float*)(sm + BAND_OFF_P);
    float* invs = (float*)(sm + BAND_OFF_I);

    const int i0 = GLB + blockIdx.x * 16;
    const int h  = blockIdx.y;
    const int b  = blockIdx.z;
    const int tid = threadIdx.x;

    const int blo = max(i0 - HALFW, GLB);
    const int bhi = min(i0 + 15 + HALFW, S_ - 1);
    const int nb  = bhi - blo + 1;

    {
        const int s = tid >> 4, f4 = tid & 15;
        float4 v = *(const float4*)(Q + ((size_t)(b * S_ + i0 + s)) * D_ + h * HD_ + f4 * 4);
        *(float4*)(Qs + s * 64 + f4 * 4) = v;
    }
    for (int task = tid; task < NC * 16; task += 256) {
        const int s = task >> 4, f4 = task & 15;
        float4 kv = make_float4(0.f, 0.f, 0.f, 0.f);
        float4 vv = make_float4(0.f, 0.f, 0.f, 0.f);
        int j = -1;
        if (s < GLB) j = s;
        else if (s - GLB < nb) j = blo + (s - GLB);
        if (j >= 0) {
            kv = *(const float4*)(K + ((size_t)(b * S_ + j)) * D_ + h * HD_ + f4 * 4);
            vv = *(const float4*)(V + ((size_t)(b * S_ + j)) * D_ + h * HD_ + f4 * 4);
        }
        float* kd = Ks + s * KPAD + f4 * 4;
        float* vd = Vs + s * KPAD + f4 * 4;
        kd[0] = kv.x; kd[1] = kv.y; kd[2] = kv.z; kd[3] = kv.w;
        vd[0] = vv.x; vd[1] = vv.y; vd[2] = vv.z; vd[3] = vv.w;
    }
    __syncthreads();

    for (int e = tid; e < 16 * NC; e += 256) {
        const int r = e / NC, c = e % NC;
        const int i = i0 + r;
        bool valid;
        if (c < GLB) valid = true;
        else {
            const int idx = c - GLB;
            const int j = blo + idx;
            valid = (idx < nb) && (j >= i - HALFW) && (j <= i + HALFW);
        }
        float s = 0.f;
        const float* kr = Ks + c * KPAD;
        const float* qr = Qs + r * 64;
#pragma unroll
        for (int d = 0; d < 64; ++d) s = fmaf(qr[d], kr[d], s);
        p[r * PPAD + c] = valid ? s * 0.125f : -1e30f;
    }
    __syncthreads();

    {
        const int w = tid >> 5, lane = tid & 31;
#pragma unroll
        for (int rr = 2 * w; rr <= 2 * w + 1; ++rr) {
            float m = -1e30f;
#pragma unroll
            for (int c = lane; c < NC; c += 32) m = fmaxf(m, p[rr * PPAD + c]);
#pragma unroll
            for (int o = 16; o; o >>= 1) m = fmaxf(m, __shfl_xor_sync(~0u, m, o));
            float sum = 0.f;
#pragma unroll
            for (int c = lane; c < NC; c += 32) {
                float e = __expf(p[rr * PPAD + c] - m);
                p[rr * PPAD + c] = e;
                sum += e;
            }
#pragma unroll
            for (int o = 16; o; o >>= 1) sum += __shfl_xor_sync(~0u, sum, o);
            if (lane == 0) invs[rr] = 1.f / sum;
        }
    }
    __syncthreads();

    {
        const int w = tid >> 5, lane = tid & 31;
#pragma unroll
        for (int rr = 2 * w; rr <= 2 * w + 1; ++rr) {
            const float inv = invs[rr];
            const float* pr = p + rr * PPAD;
            float* arow = attn + (((size_t)(b * H_ + h)) * S_ + i0 + rr) * S_;
            for (int j0 = lane * 4; j0 < S_; j0 += 128) {
                float4 o4;
                float* op = &o4.x;
#pragma unroll
                for (int u = 0; u < 4; ++u) {
                    const int j = j0 + u;
                    float v = 0.f;
                    if (j < GLB)                    v = pr[j] * inv;
                    else if (j >= blo && j <= bhi)  v = pr[GLB + j - blo] * inv;
                    op[u] = v;
                }
                *(float4*)(arow + j0) = o4;
            }
        }
    }

    {
        const int r = tid >> 4, dg = tid & 15;
        float a0 = 0.f, a1 = 0.f, a2 = 0.f, a3 = 0.f;
#pragma unroll 4
        for (int c = 0; c < NC; ++c) {
            const float wgt = p[r * PPAD + c];
            const float* vr = Vs + c * KPAD + dg * 4;
            a0 = fmaf(wgt, vr[0], a0); a1 = fmaf(wgt, vr[1], a1);
            a2 = fmaf(wgt, vr[2], a2); a3 = fmaf(wgt, vr[3], a3);
        }
        const float inv = invs[r];
        a0 *= inv; a1 *= inv; a2 *= inv; a3 *= inv;
        __nv_bfloat16 h0, h1, h2, h3, l0, l1, l2, l3;
        f2bf_hilo(a0, h0, l0); f2bf_hilo(a1, h1, l1);
        f2bf_hilo(a2, h2, l2); f2bf_hilo(a3, h3, l3);
        uint2 hp, lp;
        hp.x = (uint32_t)__bfloat16_as_ushort(h0) | ((uint32_t)__bfloat16_as_ushort(h1) << 16);
        hp.y = (uint32_t)__bfloat16_as_ushort(h2) | ((uint32_t)__bfloat16_as_ushort(h3) << 16);
        lp.x = (uint32_t)__bfloat16_as_ushort(l0) | ((uint32_t)__bfloat16_as_ushort(l1) << 16);
        lp.y = (uint32_t)__bfloat16_as_ushort(l2) | ((uint32_t)__bfloat16_as_ushort(l3) << 16);
        const size_t off = ((size_t)(b * S_ + i0 + r)) * D_ + h * HD_ + dg * 4;
        *(uint2*)(ch + off) = hp;
        *(uint2*)(cl + off) = lp;
    }
}

// ------------------------------- launch ---------------------------------------
extern "C" void kernel_launch(void* const* d_in, const int* in_sizes, int n_in,
                              void* d_out, int out_size)
{
    const float* query = (const float*)d_in[0];
    const float* key   = (const float*)d_in[1];
    const float* value = (const float*)d_in[2];
    const float* Wq = (const float*)d_in[3];
    const float* bq = (const float*)d_in[4];
    const float* Wk = (const float*)d_in[5];
    const float* bk = (const float*)d_in[6];
    const float* Wv = (const float*)d_in[7];
    const float* bv = (const float*)d_in[8];
    const float* Wo = (const float*)d_in[9];
    const float* bo = (const float*)d_in[10];

    float* out = (float*)d_out;

    float *Qp, *Kp, *Vp;
    cudaGetSymbolAddress((void**)&Qp, g_Q);
    cudaGetSymbolAddress((void**)&Kp, g_K);
    cudaGetSymbolAddress((void**)&Vp, g_V);

    __nv_bfloat16 *qh,*ql,*kh,*kl,*vh,*vl,*ch,*cl;
    __nv_bfloat16 *wqh,*wql,*wkh,*wkl,*wvh,*wvl,*woh,*wol;
    cudaGetSymbolAddress((void**)&qh, g_qh);  cudaGetSymbolAddress((void**)&ql, g_ql);
    cudaGetSymbolAddress((void**)&kh, g_kh);  cudaGetSymbolAddress((void**)&kl, g_kl);
    cudaGetSymbolAddress((void**)&vh, g_vh);  cudaGetSymbolAddress((void**)&vl, g_vl);
    cudaGetSymbolAddress((void**)&ch, g_ch);  cudaGetSymbolAddress((void**)&cl, g_cl);
    cudaGetSymbolAddress((void**)&wqh, g_wqh); cudaGetSymbolAddress((void**)&wql, g_wql);
    cudaGetSymbolAddress((void**)&wkh, g_wkh); cudaGetSymbolAddress((void**)&wkl, g_wkl);
    cudaGetSymbolAddress((void**)&wvh, g_wvh); cudaGetSymbolAddress((void**)&wvl, g_wvl);
    cudaGetSymbolAddress((void**)&woh, g_woh); cudaGetSymbolAddress((void**)&wol, g_wol);

    const size_t out_elems  = (size_t)B_ * S_ * D_;
    const size_t attn_elems = (size_t)B_ * H_ * S_ * S_;
    const bool write_attn = ((size_t)out_size >= out_elems + attn_elems);
    float* attn = write_attn ? (out + out_elems) : nullptr;

    static bool attr_done = false;
    if (!attr_done) {
        cudaFuncSetAttribute(gemm_mma, cudaFuncAttributeMaxDynamicSharedMemorySize, GEMM_SMEM);
        cudaFuncSetAttribute(attn_band, cudaFuncAttributeMaxDynamicSharedMemorySize, BAND_SMEM);
        attr_done = true;
    }

    {
        CvtArgs ci0{query, qh, ql}, ci1{key, kh, kl}, ci2{value, vh, vl};
        cvt_hilo<<<dim3(1024, 1, 3), 256>>>(ci0, ci1, ci2, ci2, MTOT * D_);
        CvtArgs cw0{Wq, wqh, wql}, cw1{Wk, wkh, wkl}, cw2{Wv, wvh, wvl}, cw3{Wo, woh, wol};
        cvt_hilo<<<dim3(512, 1, 4), 256>>>(cw0, cw1, cw2, cw3, D_ * D_);
    }

    GemmB bq_{qh, ql, wqh, wql, bq, Qp};
    GemmB bk_{kh, kl, wkh, wkl, bk, Kp};
    GemmB bv_{vh, vl, wvh, wvl, bv, Vp};

    dim3 gqkv(D_ / 128, MTOT / 128, 3);
    gemm_mma<<<gqkv, 256, GEMM_SMEM>>>(bq_, bk_, bv_);

    attn_global<<<dim3(GLB, H_, B_), 256>>>(Qp, Kp, Vp, attn, ch, cl);
    attn_band<<<dim3((S_ - GLB) / 16, H_, B_), 256, BAND_SMEM>>>(Qp, Kp, Vp, attn, ch, cl);

    GemmB bo_{ch, cl, woh, wol, bo, out};
    dim3 gout(D_ / 128, MTOT / 128, 1);
    gemm_mma<<<gout, 256, GEMM_SMEM>>>(bo_, bo_, bo_);
}

// round 9
// speedup vs baseline: 1.4747x; 1.0026x over previous
#include <cuda_runtime.h>
#include <cuda_bf16.h>
#include <math.h>
#include <stdint.h>

#define B_   2
#define S_   2048
#define D_   1024
#define H_   16
#define HD_  64
#define GLB  16
#define HALFW 32

#define MTOT (B_*S_)   // 4096

// ---------------- scratch ------------------------------------------------------
__device__ __align__(16) float g_Q[MTOT * D_];
__device__ __align__(16) float g_K[MTOT * D_];
__device__ __align__(16) float g_V[MTOT * D_];

__device__ __align__(16) __nv_bfloat16 g_qh[MTOT * D_], g_ql[MTOT * D_];
__device__ __align__(16) __nv_bfloat16 g_kh[MTOT * D_], g_kl[MTOT * D_];
__device__ __align__(16) __nv_bfloat16 g_vh[MTOT * D_], g_vl[MTOT * D_];
__device__ __align__(16) __nv_bfloat16 g_ch[MTOT * D_], g_cl[MTOT * D_];
__device__ __align__(16) __nv_bfloat16 g_wqh[D_ * D_], g_wql[D_ * D_];
__device__ __align__(16) __nv_bfloat16 g_wkh[D_ * D_], g_wkl[D_ * D_];
__device__ __align__(16) __nv_bfloat16 g_wvh[D_ * D_], g_wvl[D_ * D_];
__device__ __align__(16) __nv_bfloat16 g_woh[D_ * D_], g_wol[D_ * D_];

__device__ __forceinline__ uint32_t smem_u32(const void* p) {
    uint32_t a;
    asm("{ .reg .u64 t; cvta.to.shared.u64 t, %1; cvt.u32.u64 %0, t; }"
        : "=r"(a) : "l"(p));
    return a;
}
#define CPA16(daddr, gptr) \
    asm volatile("cp.async.ca.shared.global [%0], [%1], 16;" :: "r"(daddr), "l"(gptr))
#define CP_COMMIT() asm volatile("cp.async.commit_group;")
#define CP_WAIT1()  asm volatile("cp.async.wait_group 1;")

#define LDSM4(r0, r1, r2, r3, a) \
    asm volatile("ldmatrix.sync.aligned.m8n8.x4.shared.b16 {%0,%1,%2,%3}, [%4];" \
                 : "=r"(r0), "=r"(r1), "=r"(r2), "=r"(r3) : "r"(a))

__device__ __forceinline__ void f2bf_hilo(float x, __nv_bfloat16& h, __nv_bfloat16& l) {
    h = __float2bfloat16_rn(x);
    l = __float2bfloat16_rn(x - __bfloat162float(h));
}

// ---------------- fp32 -> bf16 hi/lo pre-convert --------------------------------
struct CvtArgs { const float* in; __nv_bfloat16* h; __nv_bfloat16* l; };

__global__ __launch_bounds__(256) void cvt_hilo(
    CvtArgs c0, CvtArgs c1, CvtArgs c2, CvtArgs c3, int n)
{
    CvtArgs c = (blockIdx.z == 0) ? c0 : (blockIdx.z == 1) ? c1 :
                (blockIdx.z == 2) ? c2 : c3;
    const int stride = gridDim.x * blockDim.x * 4;
    for (int i = (blockIdx.x * blockDim.x + threadIdx.x) * 4; i < n; i += stride) {
        float4 v = *(const float4*)(c.in + i);
        __nv_bfloat16 h0, h1, h2, h3, l0, l1, l2, l3;
        f2bf_hilo(v.x, h0, l0); f2bf_hilo(v.y, h1, l1);
        f2bf_hilo(v.z, h2, l2); f2bf_hilo(v.w, h3, l3);
        uint2 hp, lp;
        hp.x = (uint32_t)__bfloat16_as_ushort(h0) | ((uint32_t)__bfloat16_as_ushort(h1) << 16);
        hp.y = (uint32_t)__bfloat16_as_ushort(h2) | ((uint32_t)__bfloat16_as_ushort(h3) << 16);
        lp.x = (uint32_t)__bfloat16_as_ushort(l0) | ((uint32_t)__bfloat16_as_ushort(l1) << 16);
        lp.y = (uint32_t)__bfloat16_as_ushort(l2) | ((uint32_t)__bfloat16_as_ushort(l3) << 16);
        *(uint2*)(c.h + i) = hp;
        *(uint2*)(c.l + i) = lp;
    }
}

// ---------------- HMMA GEMM (bf16x3, cp.async double-buffered, ldmatrix) --------
struct GemmB {
    const __nv_bfloat16 *Ah, *Al, *Wh, *Wl;
    const float* bias;
    float* C;
};

#define SROW 40
#define SROWB (SROW * 2)                // 80 bytes
#define TILE_BYTES (128 * SROWB)        // 10240
#define GEMM_SMEM  (2 * 4 * TILE_BYTES) // 81920

__device__ __forceinline__ void mma16816(
    float& d0, float& d1, float& d2, float& d3,
    uint32_t a0, uint32_t a1, uint32_t a2, uint32_t a3,
    uint32_t b0, uint32_t b1)
{
    asm volatile(
        "mma.sync.aligned.m16n8k16.row.col.f32.bf16.bf16.f32 "
        "{%0,%1,%2,%3}, {%4,%5,%6,%7}, {%8,%9}, {%0,%1,%2,%3};"
        : "+f"(d0), "+f"(d1), "+f"(d2), "+f"(d3)
        : "r"(a0), "r"(a1), "r"(a2), "r"(a3), "r"(b0), "r"(b1));
}

__global__ __launch_bounds__(256) void gemm_mma(GemmB g0, GemmB g1, GemmB g2)
{
    GemmB g = (blockIdx.z == 0) ? g0 : ((blockIdx.z == 1) ? g1 : g2);

    extern __shared__ __align__(16) char dsm[];
    const uint32_t sb = smem_u32(dsm);

    const int tid  = threadIdx.x;
    const int wid  = tid >> 5;
    const int lane = tid & 31;
    const int bm = blockIdx.y * 128;
    const int bn = blockIdx.x * 128;
    const int warp_m = (wid & 1) * 64;
    const int warp_n = (wid >> 1) * 32;

    const int grow = tid >> 1;
    const int gk   = (tid & 1) << 4;
    const __nv_bfloat16* pAh = g.Ah + (size_t)(bm + grow) * D_ + gk;
    const __nv_bfloat16* pAl = g.Al + (size_t)(bm + grow) * D_ + gk;
    const __nv_bfloat16* pBh = g.Wh + (size_t)(bn + grow) * D_ + gk;
    const __nv_bfloat16* pBl = g.Wl + (size_t)(bn + grow) * D_ + gk;
    const uint32_t soff = (uint32_t)(grow * SROWB + gk * 2);

    float acc[4][4][4];
#pragma unroll
    for (int mt = 0; mt < 4; mt++)
#pragma unroll
        for (int nt = 0; nt < 4; nt++)
#pragma unroll
            for (int q = 0; q < 4; q++) acc[mt][nt][q] = 0.f;

    const int fr = lane >> 2;
    const int fk = (lane & 3) << 1;

    // ldmatrix lane->address components
    const int aRow  = lane & 15;               // row within 16-row tile
    const int aKoff = (lane >> 4) << 3;        // 0 or 8 (k-half)
    const int bRowO = (lane & 7) + ((lane >> 4) << 3);   // row within 16-n pair
    const int bKoff = ((lane >> 3) & 1) << 3;  // 0 or 8

#define ISSUE(chunk, stage) do {                                            \
        const int _off = (chunk) * 32;                                      \
        const uint32_t _s = sb + (stage) * 4 * TILE_BYTES + soff;           \
        CPA16(_s + 0 * TILE_BYTES,      pAh + _off);                        \
        CPA16(_s + 0 * TILE_BYTES + 16, pAh + _off + 8);                    \
        CPA16(_s + 1 * TILE_BYTES,      pAl + _off);                        \
        CPA16(_s + 1 * TILE_BYTES + 16, pAl + _off + 8);                    \
        CPA16(_s + 2 * TILE_BYTES,      pBh + _off);                        \
        CPA16(_s + 2 * TILE_BYTES + 16, pBh + _off + 8);                    \
        CPA16(_s + 3 * TILE_BYTES,      pBl + _off);                        \
        CPA16(_s + 3 * TILE_BYTES + 16, pBl + _off + 8);                    \
    } while (0)

    ISSUE(0, 0); CP_COMMIT();
    ISSUE(1, 1); CP_COMMIT();

    for (int c = 0; c < 32; ++c) {
        CP_WAIT1();
        __syncthreads();
        const uint32_t base = sb + (c & 1) * 4 * TILE_BYTES;
        const uint32_t sAh = base;
        const uint32_t sAl = base + TILE_BYTES;
        const uint32_t sBh = base + 2 * TILE_BYTES;
        const uint32_t sBl = base + 3 * TILE_BYTES;

#pragma unroll
        for (int ks = 0; ks < 2; ++ks) {
            const int kk = ks * 16;
            const uint32_t aByte = (uint32_t)((kk + aKoff) * 2);
            const uint32_t bByte = (uint32_t)((kk + bKoff) * 2);

            // A-hi fragments: one LDSM.x4 per 16-row tile
            uint32_t ah[4][4];
#pragma unroll
            for (int mt = 0; mt < 4; mt++) {
                const uint32_t addr = sAh + (uint32_t)(warp_m + mt * 16 + aRow) * SROWB + aByte;
                LDSM4(ah[mt][0], ah[mt][1], ah[mt][2], ah[mt][3], addr);
            }
            // B-hi fragments: one LDSM.x4 per pair of 8-n tiles
            uint32_t bh[4][2];
#pragma unroll
            for (int p = 0; p < 2; p++) {
                const uint32_t addr = sBh + (uint32_t)(warp_n + p * 16 + bRowO) * SROWB + bByte;
                LDSM4(bh[2 * p][0], bh[2 * p][1], bh[2 * p + 1][0], bh[2 * p + 1][1], addr);
            }
            // pass 1: Ah x Bh
#pragma unroll
            for (int mt = 0; mt < 4; mt++)
#pragma unroll
                for (int nt = 0; nt < 4; nt++)
                    mma16816(acc[mt][nt][0], acc[mt][nt][1], acc[mt][nt][2], acc[mt][nt][3],
                             ah[mt][0], ah[mt][1], ah[mt][2], ah[mt][3],
                             bh[nt][0], bh[nt][1]);
            // pass 2: Al x Bh
#pragma unroll
            for (int mt = 0; mt < 4; mt++) {
                uint32_t al0, al1, al2, al3;
                const uint32_t addr = sAl + (uint32_t)(warp_m + mt * 16 + aRow) * SROWB + aByte;
                LDSM4(al0, al1, al2, al3, addr);
#pragma unroll
                for (int nt = 0; nt < 4; nt++)
                    mma16816(acc[mt][nt][0], acc[mt][nt][1], acc[mt][nt][2], acc[mt][nt][3],
                             al0, al1, al2, al3, bh[nt][0], bh[nt][1]);
            }
            // pass 3: Ah x Bl
#pragma unroll
            for (int p = 0; p < 2; p++) {
                uint32_t bl00, bl01, bl10, bl11;
                const uint32_t addr = sBl + (uint32_t)(warp_n + p * 16 + bRowO) * SROWB + bByte;
                LDSM4(bl00, bl01, bl10, bl11, addr);
#pragma unroll
                for (int mt = 0; mt < 4; mt++) {
                    mma16816(acc[mt][2 * p][0], acc[mt][2 * p][1], acc[mt][2 * p][2], acc[mt][2 * p][3],
                             ah[mt][0], ah[mt][1], ah[mt][2], ah[mt][3], bl00, bl01);
                    mma16816(acc[mt][2 * p + 1][0], acc[mt][2 * p + 1][1], acc[mt][2 * p + 1][2], acc[mt][2 * p + 1][3],
                             ah[mt][0], ah[mt][1], ah[mt][2], ah[mt][3], bl10, bl11);
                }
            }
        }
        __syncthreads();
        if (c + 2 < 32) ISSUE(c + 2, c & 1);
        CP_COMMIT();
    }
#undef ISSUE

#pragma unroll
    for (int mt = 0; mt < 4; mt++) {
        const int r0 = bm + warp_m + mt * 16 + fr;
#pragma unroll
        for (int nt = 0; nt < 4; nt++) {
            const int col = bn + warp_n + nt * 8 + fk;
            const float b0 = g.bias[col], b1 = g.bias[col + 1];
            float2 v0 = make_float2(acc[mt][nt][0] + b0, acc[mt][nt][1] + b1);
            float2 v1 = make_float2(acc[mt][nt][2] + b0, acc[mt][nt][3] + b1);
            *(float2*)(g.C + (size_t)r0 * D_ + col)       = v0;
            *(float2*)(g.C + (size_t)(r0 + 8) * D_ + col) = v1;
        }
    }
}

// ---------------- global-query attention: one block per (b, h, row) -----------
__global__ __launch_bounds__(256) void attn_global(
    const float* __restrict__ Q, const float* __restrict__ K,
    const float* __restrict__ V, float* __restrict__ attn,
    __nv_bfloat16* __restrict__ ch, __nv_bfloat16* __restrict__ cl)
{
    const int i = blockIdx.x;
    const int h = blockIdx.y;
    const int b = blockIdx.z;
    const int tid = threadIdx.x;
    const int wid = tid >> 5;
    const int lane = tid & 31;

    __shared__ __align__(16) float qs[HD_];
    __shared__ float p[S_];
    __shared__ float red[8];
    __shared__ float sb;
    __shared__ __align__(16) float cpart[8][HD_];

    const float* qrow = Q + ((size_t)(b * S_ + i)) * D_ + h * HD_;
    if (tid < HD_) qs[tid] = qrow[tid];
    __syncthreads();

    const int hw = lane >> 4;
    const int t  = lane & 15;
    const float4 qv = *(const float4*)(qs + t * 4);
    float lmax = -1e30f;
    const float* kbase = K + ((size_t)(b * S_)) * D_ + h * HD_ + t * 4;
    for (int j = wid * 2 + hw; j < S_; j += 16) {
        float4 kv = *(const float4*)(kbase + (size_t)j * D_);
        float s = kv.x * qv.x + kv.y * qv.y + kv.z * qv.z + kv.w * qv.w;
#pragma unroll
        for (int o = 8; o; o >>= 1) s += __shfl_xor_sync(~0u, s, o);
        s *= 0.125f;
        if (t == 0) p[j] = s;
        lmax = fmaxf(lmax, s);
    }
#pragma unroll
    for (int o = 16; o; o >>= 1) lmax = fmaxf(lmax, __shfl_xor_sync(~0u, lmax, o));
    if (lane == 0) red[wid] = lmax;
    __syncthreads();
    if (tid == 0) {
        float m = red[0];
#pragma unroll
        for (int w = 1; w < 8; ++w) m = fmaxf(m, red[w]);
        sb = m;
    }
    __syncthreads();
    const float m = sb;
    __syncthreads();

    float lsum = 0.f;
    for (int j = tid; j < S_; j += 256) { float e = __expf(p[j] - m); p[j] = e; lsum += e; }
#pragma unroll
    for (int o = 16; o; o >>= 1) lsum += __shfl_xor_sync(~0u, lsum, o);
    if (lane == 0) red[wid] = lsum;
    __syncthreads();
    if (tid == 0) {
        float s = red[0];
#pragma unroll
        for (int w = 1; w < 8; ++w) s += red[w];
        sb = 1.f / s;
    }
    __syncthreads();
    const float inv = sb;

    {
        float* arow = attn + (((size_t)(b * H_ + h)) * S_ + i) * S_;
        for (int j0 = tid * 4; j0 < S_; j0 += 256 * 4) {
            float4 o4;
            o4.x = p[j0 + 0] * inv; o4.y = p[j0 + 1] * inv;
            o4.z = p[j0 + 2] * inv; o4.w = p[j0 + 3] * inv;
            *(float4*)(arow + j0) = o4;
        }
    }

    {
        const float* vbase = V + ((size_t)(b * S_)) * D_ + h * HD_ + lane * 2;
        float a0 = 0.f, a1 = 0.f, b0 = 0.f, b1 = 0.f;
        const int j0 = wid * 256;
#pragma unroll 4
        for (int j = j0; j < j0 + 256; j += 2) {
            float2 v0 = *(const float2*)(vbase + (size_t)j * D_);
            float2 v1 = *(const float2*)(vbase + (size_t)(j + 1) * D_);
            const float p0 = p[j], p1 = p[j + 1];
            a0 = fmaf(p0, v0.x, a0); a1 = fmaf(p0, v0.y, a1);
            b0 = fmaf(p1, v1.x, b0); b1 = fmaf(p1, v1.y, b1);
        }
        cpart[wid][lane * 2]     = a0 + b0;
        cpart[wid][lane * 2 + 1] = a1 + b1;
        __syncthreads();
        if (tid < HD_) {
            float s = 0.f;
#pragma unroll
            for (int w = 0; w < 8; ++w) s += cpart[w][tid];
            s *= inv;
            __nv_bfloat16 hh, ll;
            f2bf_hilo(s, hh, ll);
            const size_t off = ((size_t)(b * S_ + i)) * D_ + h * HD_ + tid;
            ch[off] = hh; cl[off] = ll;
        }
    }
}

// ---------------- banded attention: 16 query rows per block -------------------
#define NC 96
#define KPAD 65
#define PPAD 97
#define BAND_OFF_Q  0
#define BAND_OFF_K  (16*64*4)
#define BAND_OFF_V  (BAND_OFF_K + NC*KPAD*4)
#define BAND_OFF_P  (BAND_OFF_V + NC*KPAD*4)
#define BAND_OFF_I  (BAND_OFF_P + 16*PPAD*4)
#define BAND_SMEM   (BAND_OFF_I + 64)

__global__ __launch_bounds__(256) void attn_band(
    const float* __restrict__ Q, const float* __restrict__ K,
    const float* __restrict__ V, float* __restrict__ attn,
    __nv_bfloat16* __restrict__ ch, __nv_bfloat16* __restrict__ cl)
{
    extern __shared__ __align__(16) char sm[];
    float* Qs = (float*)(sm + BAND_OFF_Q);
    float* Ks = (float*)(sm + BAND_OFF_K);
    float* Vs = (float*)(sm + BAND_OFF_V);
    float* p  = (float*)(sm + BAND_OFF_P);
    float* invs = (float*)(sm + BAND_OFF_I);

    const int i0 = GLB + blockIdx.x * 16;
    const int h  = blockIdx.y;
    const int b  = blockIdx.z;
    const int tid = threadIdx.x;

    const int blo = max(i0 - HALFW, GLB);
    const int bhi = min(i0 + 15 + HALFW, S_ - 1);
    const int nb  = bhi - blo + 1;

    {
        const int s = tid >> 4, f4 = tid & 15;
        float4 v = *(const float4*)(Q + ((size_t)(b * S_ + i0 + s)) * D_ + h * HD_ + f4 * 4);
        *(float4*)(Qs + s * 64 + f4 * 4) = v;
    }
    for (int task = tid; task < NC * 16; task += 256) {
        const int s = task >> 4, f4 = task & 15;
        float4 kv = make_float4(0.f, 0.f, 0.f, 0.f);
        float4 vv = make_float4(0.f, 0.f, 0.f, 0.f);
        int j = -1;
        if (s < GLB) j = s;
        else if (s - GLB < nb) j = blo + (s - GLB);
        if (j >= 0) {
            kv = *(const float4*)(K + ((size_t)(b * S_ + j)) * D_ + h * HD_ + f4 * 4);
            vv = *(const float4*)(V + ((size_t)(b * S_ + j)) * D_ + h * HD_ + f4 * 4);
        }
        float* kd = Ks + s * KPAD + f4 * 4;
        float* vd = Vs + s * KPAD + f4 * 4;
        kd[0] = kv.x; kd[1] = kv.y; kd[2] = kv.z; kd[3] = kv.w;
        vd[0] = vv.x; vd[1] = vv.y; vd[2] = vv.z; vd[3] = vv.w;
    }
    __syncthreads();

    for (int e = tid; e < 16 * NC; e += 256) {
        const int r = e / NC, c = e % NC;
        const int i = i0 + r;
        bool valid;
        if (c < GLB) valid = true;
        else {
            const int idx = c - GLB;
            const int j = blo + idx;
            valid = (idx < nb) && (j >= i - HALFW) && (j <= i + HALFW);
        }
        float s = 0.f;
        const float* kr = Ks + c * KPAD;
        const float* qr = Qs + r * 64;
#pragma unroll
        for (int d = 0; d < 64; ++d) s = fmaf(qr[d], kr[d], s);
        p[r * PPAD + c] = valid ? s * 0.125f : -1e30f;
    }
    __syncthreads();

    {
        const int w = tid >> 5, lane = tid & 31;
#pragma unroll
        for (int rr = 2 * w; rr <= 2 * w + 1; ++rr) {
            float m = -1e30f;
#pragma unroll
            for (int c = lane; c < NC; c += 32) m = fmaxf(m, p[rr * PPAD + c]);
#pragma unroll
            for (int o = 16; o; o >>= 1) m = fmaxf(m, __shfl_xor_sync(~0u, m, o));
            float sum = 0.f;
#pragma unroll
            for (int c = lane; c < NC; c += 32) {
                float e = __expf(p[rr * PPAD + c] - m);
                p[rr * PPAD + c] = e;
                sum += e;
            }
#pragma unroll
            for (int o = 16; o; o >>= 1) sum += __shfl_xor_sync(~0u, sum, o);
            if (lane == 0) invs[rr] = 1.f / sum;
        }
    }
    __syncthreads();

    {
        const int w = tid >> 5, lane = tid & 31;
#pragma unroll
        for (int rr = 2 * w; rr <= 2 * w + 1; ++rr) {
            const float inv = invs[rr];
            const float* pr = p + rr * PPAD;
            float* arow = attn + (((size_t)(b * H_ + h)) * S_ + i0 + rr) * S_;
            for (int j0 = lane * 4; j0 < S_; j0 += 128) {
                float4 o4;
                float* op = &o4.x;
#pragma unroll
                for (int u = 0; u < 4; ++u) {
                    const int j = j0 + u;
                    float v = 0.f;
                    if (j < GLB)                    v = pr[j] * inv;
                    else if (j >= blo && j <= bhi)  v = pr[GLB + j - blo] * inv;
                    op[u] = v;
                }
                *(float4*)(arow + j0) = o4;
            }
        }
    }

    {
        const int r = tid >> 4, dg = tid & 15;
        float a0 = 0.f, a1 = 0.f, a2 = 0.f, a3 = 0.f;
#pragma unroll 4
        for (int c = 0; c < NC; ++c) {
            const float wgt = p[r * PPAD + c];
            const float* vr = Vs + c * KPAD + dg * 4;
            a0 = fmaf(wgt, vr[0], a0); a1 = fmaf(wgt, vr[1], a1);
            a2 = fmaf(wgt, vr[2], a2); a3 = fmaf(wgt, vr[3], a3);
        }
        const float inv = invs[r];
        a0 *= inv; a1 *= inv; a2 *= inv; a3 *= inv;
        __nv_bfloat16 h0, h1, h2, h3, l0, l1, l2, l3;
        f2bf_hilo(a0, h0, l0); f2bf_hilo(a1, h1, l1);
        f2bf_hilo(a2, h2, l2); f2bf_hilo(a3, h3, l3);
        uint2 hp, lp;
        hp.x = (uint32_t)__bfloat16_as_ushort(h0) | ((uint32_t)__bfloat16_as_ushort(h1) << 16);
        hp.y = (uint32_t)__bfloat16_as_ushort(h2) | ((uint32_t)__bfloat16_as_ushort(h3) << 16);
        lp.x = (uint32_t)__bfloat16_as_ushort(l0) | ((uint32_t)__bfloat16_as_ushort(l1) << 16);
        lp.y = (uint32_t)__bfloat16_as_ushort(l2) | ((uint32_t)__bfloat16_as_ushort(l3) << 16);
        const size_t off = ((size_t)(b * S_ + i0 + r)) * D_ + h * HD_ + dg * 4;
        *(uint2*)(ch + off) = hp;
        *(uint2*)(cl + off) = lp;
    }
}

// ------------------------------- launch ---------------------------------------
extern "C" void kernel_launch(void* const* d_in, const int* in_sizes, int n_in,
                              void* d_out, int out_size)
{
    const float* query = (const float*)d_in[0];
    const float* key   = (const float*)d_in[1];
    const float* value = (const float*)d_in[2];
    const float* Wq = (const float*)d_in[3];
    const float* bq = (const float*)d_in[4];
    const float* Wk = (const float*)d_in[5];
    const float* bk = (const float*)d_in[6];
    const float* Wv = (const float*)d_in[7];
    const float* bv = (const float*)d_in[8];
    const float* Wo = (const float*)d_in[9];
    const float* bo = (const float*)d_in[10];

    float* out = (float*)d_out;

    float *Qp, *Kp, *Vp;
    cudaGetSymbolAddress((void**)&Qp, g_Q);
    cudaGetSymbolAddress((void**)&Kp, g_K);
    cudaGetSymbolAddress((void**)&Vp, g_V);

    __nv_bfloat16 *qh,*ql,*kh,*kl,*vh,*vl,*ch,*cl;
    __nv_bfloat16 *wqh,*wql,*wkh,*wkl,*wvh,*wvl,*woh,*wol;
    cudaGetSymbolAddress((void**)&qh, g_qh);  cudaGetSymbolAddress((void**)&ql, g_ql);
    cudaGetSymbolAddress((void**)&kh, g_kh);  cudaGetSymbolAddress((void**)&kl, g_kl);
    cudaGetSymbolAddress((void**)&vh, g_vh);  cudaGetSymbolAddress((void**)&vl, g_vl);
    cudaGetSymbolAddress((void**)&ch, g_ch);  cudaGetSymbolAddress((void**)&cl, g_cl);
    cudaGetSymbolAddress((void**)&wqh, g_wqh); cudaGetSymbolAddress((void**)&wql, g_wql);
    cudaGetSymbolAddress((void**)&wkh, g_wkh); cudaGetSymbolAddress((void**)&wkl, g_wkl);
    cudaGetSymbolAddress((void**)&wvh, g_wvh); cudaGetSymbolAddress((void**)&wvl, g_wvl);
    cudaGetSymbolAddress((void**)&woh, g_woh); cudaGetSymbolAddress((void**)&wol, g_wol);

    const size_t out_elems  = (size_t)B_ * S_ * D_;
    const size_t attn_elems = (size_t)B_ * H_ * S_ * S_;
    const bool write_attn = ((size_t)out_size >= out_elems + attn_elems);
    float* attn = write_attn ? (out + out_elems) : nullptr;

    static bool attr_done = false;
    if (!attr_done) {
        cudaFuncSetAttribute(gemm_mma, cudaFuncAttributeMaxDynamicSharedMemorySize, GEMM_SMEM);
        cudaFuncSetAttribute(attn_band, cudaFuncAttributeMaxDynamicSharedMemorySize, BAND_SMEM);
        attr_done = true;
    }

    {
        CvtArgs ci0{query, qh, ql}, ci1{key, kh, kl}, ci2{value, vh, vl};
        cvt_hilo<<<dim3(1024, 1, 3), 256>>>(ci0, ci1, ci2, ci2, MTOT * D_);
        CvtArgs cw0{Wq, wqh, wql}, cw1{Wk, wkh, wkl}, cw2{Wv, wvh, wvl}, cw3{Wo, woh, wol};
        cvt_hilo<<<dim3(512, 1, 4), 256>>>(cw0, cw1, cw2, cw3, D_ * D_);
    }

    GemmB bq_{qh, ql, wqh, wql, bq, Qp};
    GemmB bk_{kh, kl, wkh, wkl, bk, Kp};
    GemmB bv_{vh, vl, wvh, wvl, bv, Vp};

    dim3 gqkv(D_ / 128, MTOT / 128, 3);
    gemm_mma<<<gqkv, 256, GEMM_SMEM>>>(bq_, bk_, bv_);

    attn_global<<<dim3(GLB, H_, B_), 256>>>(Qp, Kp, Vp, attn, ch, cl);
    attn_band<<<dim3((S_ - GLB) / 16, H_, B_), 256, BAND_SMEM>>>(Qp, Kp, Vp, attn, ch, cl);

    GemmB bo_{ch, cl, woh, wol, bo, out};
    dim3 gout(D_ / 128, MTOT / 128, 1);
    gemm_mma<<<gout, 256, GEMM_SMEM>>>(bo_, bo_, bo_);
}